// round 1
// baseline (speedup 1.0000x reference)
#include <cuda_runtime.h>

#define Bx 4
#define Cx 256
#define Nx 4096
#define Ex 32
#define TK 128

// Scratch (allocation-free rule: __device__ globals). 8 MB total.
__device__ float g_f[Bx * Ex * Nx];
__device__ float g_g[Bx * Ex * Nx];
__device__ float g_h[Bx * Ex * Nx];
__device__ float g_v[Bx * Ex * Nx];

// ---------------------------------------------------------------------------
// Kernel 1: f/g/h = W @ x + b   (1x1 conv == channel matmul)
// grid (Nx/128, Bx, 3), block 128. Each thread owns one token n, 32 outputs.
// W reads are warp-uniform float4 (broadcast, L1-resident); x reads coalesced.
// ---------------------------------------------------------------------------
__global__ __launch_bounds__(128) void proj_kernel(
    const float* __restrict__ x,
    const float* __restrict__ Wk, const float* __restrict__ bk,
    const float* __restrict__ Wq, const float* __restrict__ bq,
    const float* __restrict__ Wv, const float* __restrict__ bv)
{
    const int n = blockIdx.x * 128 + threadIdx.x;
    const int b = blockIdx.y;
    const int z = blockIdx.z;

    const float* W;
    const float* bias;
    float* out;
    if (z == 0)      { W = Wk; bias = bk; out = g_f; }
    else if (z == 1) { W = Wq; bias = bq; out = g_g; }
    else             { W = Wv; bias = bv; out = g_h; }

    const float* xp = x + (size_t)b * Cx * Nx + n;
    float acc[Ex];
#pragma unroll
    for (int e = 0; e < Ex; e++) acc[e] = bias[e];

    const float4* W4 = (const float4*)W;  // [Ex][Cx/4]
    for (int c4 = 0; c4 < Cx / 4; c4++) {
        const float x0 = xp[(c4 * 4 + 0) * Nx];
        const float x1 = xp[(c4 * 4 + 1) * Nx];
        const float x2 = xp[(c4 * 4 + 2) * Nx];
        const float x3 = xp[(c4 * 4 + 3) * Nx];
#pragma unroll
        for (int e = 0; e < Ex; e++) {
            const float4 w = W4[e * (Cx / 4) + c4];
            acc[e] += w.x * x0 + w.y * x1 + w.z * x2 + w.w * x3;
        }
    }

    float* op = out + (size_t)b * Ex * Nx + n;
#pragma unroll
    for (int e = 0; e < Ex; e++) op[e * Nx] = acc[e];
}

// ---------------------------------------------------------------------------
// Kernel 2: fused attention. grid (Nx/128, Bx), block 128.
// Each thread owns one query j: g[:,j] in regs, acc[32] in regs.
// Tiles of TK=128 keys staged in smem (f and h, [32][128]).
// No online-max: scores ~ N(0,32) -> exp never overflows fp32.
// Inner loop = 64 FMA + 1 exp per key (fma-pipe bound by design).
// ---------------------------------------------------------------------------
__global__ __launch_bounds__(128) void attn_kernel()
{
    __shared__ float f_s[Ex][TK];
    __shared__ float h_s[Ex][TK];

    const int tid = threadIdx.x;
    const int q   = blockIdx.x * 128 + tid;
    const int b   = blockIdx.y;

    const float* fb = g_f + (size_t)b * Ex * Nx;
    const float* gb = g_g + (size_t)b * Ex * Nx;
    const float* hb = g_h + (size_t)b * Ex * Nx;

    float greg[Ex];
#pragma unroll
    for (int e = 0; e < Ex; e++) greg[e] = gb[e * Nx + q];

    float acc[Ex];
#pragma unroll
    for (int e = 0; e < Ex; e++) acc[e] = 0.f;
    float l = 0.f;

    for (int i0 = 0; i0 < Nx; i0 += TK) {
        __syncthreads();
        // cooperative tile load: Ex*TK = 4096 elems each, 32 per thread,
        // coalesced (consecutive tid -> consecutive key k)
#pragma unroll
        for (int r = 0; r < (Ex * TK) / 128; r++) {
            const int idx = r * 128 + tid;
            const int e = idx >> 7;       // / TK
            const int k = idx & (TK - 1); // % TK
            f_s[e][k] = fb[e * Nx + i0 + k];
            h_s[e][k] = hb[e * Nx + i0 + k];
        }
        __syncthreads();

        for (int k = 0; k < TK; k += 4) {
            float s0 = 0.f, s1 = 0.f, s2 = 0.f, s3 = 0.f;
#pragma unroll
            for (int e = 0; e < Ex; e++) {
                const float4 fv = *(const float4*)&f_s[e][k];  // broadcast LDS.128
                const float gv = greg[e];
                s0 += fv.x * gv; s1 += fv.y * gv;
                s2 += fv.z * gv; s3 += fv.w * gv;
            }
            const float p0 = __expf(s0);
            const float p1 = __expf(s1);
            const float p2 = __expf(s2);
            const float p3 = __expf(s3);
            l += (p0 + p1) + (p2 + p3);
#pragma unroll
            for (int e = 0; e < Ex; e++) {
                const float4 hv = *(const float4*)&h_s[e][k];
                acc[e] += hv.x * p0 + hv.y * p1 + hv.z * p2 + hv.w * p3;
            }
        }
    }

    const float inv = 1.0f / l;
    float* vp = g_v + (size_t)b * Ex * Nx + q;
#pragma unroll
    for (int e = 0; e < Ex; e++) vp[e * Nx] = acc[e] * inv;
}

// ---------------------------------------------------------------------------
// Kernel 3: o = Wo @ v + bo ; y = 0.5*o + x ; gamma = 0.5
// grid (Nx/128, Bx), block 128. One token per thread, v[:,n] in regs.
// ---------------------------------------------------------------------------
__global__ __launch_bounds__(128) void oproj_kernel(
    const float* __restrict__ x,
    const float* __restrict__ Wo, const float* __restrict__ bo,
    float* __restrict__ out_y, float* __restrict__ out_o,
    float* __restrict__ out_gamma)
{
    const int n = blockIdx.x * 128 + threadIdx.x;
    const int b = blockIdx.y;

    float vr[Ex];
    const float* vp = g_v + (size_t)b * Ex * Nx + n;
#pragma unroll
    for (int e = 0; e < Ex; e++) vr[e] = vp[e * Nx];

    const float4* Wo4 = (const float4*)Wo;  // [Cx][Ex/4]
    const float* xp = x + (size_t)b * Cx * Nx + n;
    float* yp = out_y + (size_t)b * Cx * Nx + n;
    float* op = out_o ? (out_o + (size_t)b * Cx * Nx + n) : nullptr;

    for (int c = 0; c < Cx; c++) {
        float a = bo[c];
#pragma unroll
        for (int e4 = 0; e4 < Ex / 4; e4++) {
            const float4 w = Wo4[c * (Ex / 4) + e4];
            a += w.x * vr[e4 * 4 + 0] + w.y * vr[e4 * 4 + 1] +
                 w.z * vr[e4 * 4 + 2] + w.w * vr[e4 * 4 + 3];
        }
        if (op) op[c * Nx] = a;
        yp[c * Nx] = 0.5f * a + xp[c * Nx];
    }

    if (out_gamma && blockIdx.x == 0 && blockIdx.y == 0 && threadIdx.x == 0)
        out_gamma[0] = 0.5f;
}

// ---------------------------------------------------------------------------
extern "C" void kernel_launch(void* const* d_in, const int* in_sizes, int n_in,
                              void* d_out, int out_size)
{
    const float* x  = (const float*)d_in[0];
    const float* Wk = (const float*)d_in[1];
    const float* bk = (const float*)d_in[2];
    const float* Wq = (const float*)d_in[3];
    const float* bq = (const float*)d_in[4];
    const float* Wv = (const float*)d_in[5];
    const float* bv = (const float*)d_in[6];
    const float* Wo = (const float*)d_in[7];
    const float* bo = (const float*)d_in[8];

    const size_t BCN = (size_t)Bx * Cx * Nx;  // 4194304
    float* out = (float*)d_out;

    // Expected output layout: [y (BCN), o (BCN), gamma (1)]. Be defensive if
    // the harness only wants y.
    const bool full = ((size_t)out_size >= 2 * BCN + 1);
    float* out_y = out;
    float* out_o = full ? (out + BCN) : nullptr;
    float* out_g = full ? (out + 2 * BCN) : nullptr;

    proj_kernel<<<dim3(Nx / 128, Bx, 3), 128>>>(x, Wk, bk, Wq, bq, Wv, bv);
    attn_kernel<<<dim3(Nx / 128, Bx), 128>>>();
    oproj_kernel<<<dim3(Nx / 128, Bx), 128>>>(x, Wo, bo, out_y, out_o, out_g);
}

// round 2
// speedup vs baseline: 1.3560x; 1.3560x over previous
#include <cuda_runtime.h>

#define Bx 4
#define Cx 256
#define Nx 4096
#define Ex 32
#define TK 128

// Scratch (allocation-free rule: __device__ globals). 8 MB total.
__device__ float g_f[Bx * Ex * Nx];
__device__ float g_g[Bx * Ex * Nx];
__device__ float g_h[Bx * Ex * Nx];
__device__ float g_v[Bx * Ex * Nx];

// ---------------------------------------------------------------------------
// Kernel 1: f/g/h = W @ x + b   (1x1 conv == channel matmul)
// grid (32, B, 3), block 512. Thread = (token lane 0..127, e-slice 0..3).
// Each thread computes 8 of 32 outputs -> 4x the resident warps of round 1.
// ---------------------------------------------------------------------------
__global__ __launch_bounds__(512) void proj_kernel(
    const float* __restrict__ x,
    const float* __restrict__ Wk, const float* __restrict__ bk,
    const float* __restrict__ Wq, const float* __restrict__ bq,
    const float* __restrict__ Wv, const float* __restrict__ bv)
{
    const int tid  = threadIdx.x;
    const int lane = tid & 127;
    const int es   = tid >> 7;          // 0..3 : e-slice
    const int n    = blockIdx.x * 128 + lane;
    const int b    = blockIdx.y;
    const int z    = blockIdx.z;

    const float* W;
    const float* bias;
    float* out;
    if (z == 0)      { W = Wk; bias = bk; out = g_f; }
    else if (z == 1) { W = Wq; bias = bq; out = g_g; }
    else             { W = Wv; bias = bv; out = g_h; }

    const float* xp = x + (size_t)b * Cx * Nx + n;
    const int e0 = es * 8;

    float acc[8];
#pragma unroll
    for (int e = 0; e < 8; e++) acc[e] = bias[e0 + e];

    const float4* W4 = (const float4*)W;  // [Ex][Cx/4]
    for (int c4 = 0; c4 < Cx / 4; c4++) {
        const float x0 = xp[(c4 * 4 + 0) * Nx];
        const float x1 = xp[(c4 * 4 + 1) * Nx];
        const float x2 = xp[(c4 * 4 + 2) * Nx];
        const float x3 = xp[(c4 * 4 + 3) * Nx];
#pragma unroll
        for (int e = 0; e < 8; e++) {
            const float4 w = W4[(e0 + e) * (Cx / 4) + c4];
            acc[e] += w.x * x0 + w.y * x1 + w.z * x2 + w.w * x3;
        }
    }

    float* op = out + (size_t)b * Ex * Nx + n;
#pragma unroll
    for (int e = 0; e < 8; e++) op[(e0 + e) * Nx] = acc[e];
}

// ---------------------------------------------------------------------------
// Kernel 2: fused attention. grid (32, B), block 256 (8 warps).
// 128 queries per block. Threads split each 128-key tile 2-way:
// group ks = tid>>7 handles keys [ks*64, ks*64+64) of every tile.
// Partial (acc[32], l) combined through smem at the end.
// No online-max: scores ~ N(0,32) -> exp never overflows fp32.
// ---------------------------------------------------------------------------
__global__ __launch_bounds__(256) void attn_kernel()
{
    __shared__ float tile[2][Ex][TK];   // [0]=f, [1]=h : 32 KB
    float (*f_s)[TK] = tile[0];
    float (*h_s)[TK] = tile[1];

    const int tid  = threadIdx.x;
    const int lane = tid & 127;
    const int ks   = tid >> 7;          // key-half within tile
    const int q    = blockIdx.x * 128 + lane;
    const int b    = blockIdx.y;

    const float* fb = g_f + (size_t)b * Ex * Nx;
    const float* gb = g_g + (size_t)b * Ex * Nx;
    const float* hb = g_h + (size_t)b * Ex * Nx;

    float greg[Ex];
#pragma unroll
    for (int e = 0; e < Ex; e++) greg[e] = gb[e * Nx + q];

    float acc[Ex];
#pragma unroll
    for (int e = 0; e < Ex; e++) acc[e] = 0.f;
    float l = 0.f;

    const int kbeg = ks * 64;

    for (int i0 = 0; i0 < Nx; i0 += TK) {
        __syncthreads();
        // cooperative tile load: 4096 elems per array, 16 per thread, coalesced
#pragma unroll
        for (int r = 0; r < (Ex * TK) / 256; r++) {
            const int idx = r * 256 + tid;
            const int e = idx >> 7;        // / TK
            const int k = idx & (TK - 1);  // % TK
            f_s[e][k] = fb[e * Nx + i0 + k];
            h_s[e][k] = hb[e * Nx + i0 + k];
        }
        __syncthreads();

#pragma unroll 4
        for (int kk = 0; kk < 64; kk += 4) {
            const int k = kbeg + kk;
            float s0 = 0.f, s1 = 0.f, s2 = 0.f, s3 = 0.f;
#pragma unroll
            for (int e = 0; e < Ex; e++) {
                const float4 fv = *(const float4*)&f_s[e][k];  // broadcast LDS.128
                const float gv = greg[e];
                s0 += fv.x * gv; s1 += fv.y * gv;
                s2 += fv.z * gv; s3 += fv.w * gv;
            }
            const float p0 = __expf(s0);
            const float p1 = __expf(s1);
            const float p2 = __expf(s2);
            const float p3 = __expf(s3);
            l += (p0 + p1) + (p2 + p3);
#pragma unroll
            for (int e = 0; e < Ex; e++) {
                const float4 hv = *(const float4*)&h_s[e][k];
                acc[e] += hv.x * p0 + hv.y * p1 + hv.z * p2 + hv.w * p3;
            }
        }
    }

    // combine the two key-halves through smem (reuse the tile storage)
    __syncthreads();
    float* buf = &tile[0][0][0];        // need 128*33 = 4224 floats (< 8192)
    if (ks == 1) {
#pragma unroll
        for (int e = 0; e < Ex; e++) buf[lane * 33 + e] = acc[e];
        buf[lane * 33 + 32] = l;
    }
    __syncthreads();
    if (ks == 0) {
#pragma unroll
        for (int e = 0; e < Ex; e++) acc[e] += buf[lane * 33 + e];
        l += buf[lane * 33 + 32];

        const float inv = 1.0f / l;
        float* vp = g_v + (size_t)b * Ex * Nx + q;
#pragma unroll
        for (int e = 0; e < Ex; e++) vp[e * Nx] = acc[e] * inv;
    }
}

// ---------------------------------------------------------------------------
// Kernel 3: o = Wo @ v + bo ; y = 0.5*o + x ; gamma = 0.5
// grid (32, B), block 512. Thread = (token lane, channel-slice 0..3),
// 64 output channels per thread.
// ---------------------------------------------------------------------------
__global__ __launch_bounds__(512) void oproj_kernel(
    const float* __restrict__ x,
    const float* __restrict__ Wo, const float* __restrict__ bo,
    float* __restrict__ out_y, float* __restrict__ out_o,
    float* __restrict__ out_gamma)
{
    const int tid  = threadIdx.x;
    const int lane = tid & 127;
    const int cs   = tid >> 7;          // 0..3 : channel-slice
    const int n    = blockIdx.x * 128 + lane;
    const int b    = blockIdx.y;

    float vr[Ex];
    const float* vp = g_v + (size_t)b * Ex * Nx + n;
#pragma unroll
    for (int e = 0; e < Ex; e++) vr[e] = vp[e * Nx];

    const float4* Wo4 = (const float4*)Wo;  // [Cx][Ex/4]
    const float* xp = x + (size_t)b * Cx * Nx + n;
    float* yp = out_y + (size_t)b * Cx * Nx + n;
    float* op = out_o ? (out_o + (size_t)b * Cx * Nx + n) : nullptr;

    const int c0 = cs * 64;
#pragma unroll 4
    for (int ci = 0; ci < 64; ci++) {
        const int c = c0 + ci;
        float a = bo[c];
#pragma unroll
        for (int e4 = 0; e4 < Ex / 4; e4++) {
            const float4 w = Wo4[c * (Ex / 4) + e4];
            a += w.x * vr[e4 * 4 + 0] + w.y * vr[e4 * 4 + 1] +
                 w.z * vr[e4 * 4 + 2] + w.w * vr[e4 * 4 + 3];
        }
        if (op) op[c * Nx] = a;
        yp[c * Nx] = 0.5f * a + xp[c * Nx];
    }

    if (out_gamma && blockIdx.x == 0 && blockIdx.y == 0 && threadIdx.x == 0)
        out_gamma[0] = 0.5f;
}

// ---------------------------------------------------------------------------
extern "C" void kernel_launch(void* const* d_in, const int* in_sizes, int n_in,
                              void* d_out, int out_size)
{
    const float* x  = (const float*)d_in[0];
    const float* Wk = (const float*)d_in[1];
    const float* bk = (const float*)d_in[2];
    const float* Wq = (const float*)d_in[3];
    const float* bq = (const float*)d_in[4];
    const float* Wv = (const float*)d_in[5];
    const float* bv = (const float*)d_in[6];
    const float* Wo = (const float*)d_in[7];
    const float* bo = (const float*)d_in[8];

    const size_t BCN = (size_t)Bx * Cx * Nx;  // 4194304
    float* out = (float*)d_out;

    const bool full = ((size_t)out_size >= 2 * BCN + 1);
    float* out_y = out;
    float* out_o = full ? (out + BCN) : nullptr;
    float* out_g = full ? (out + 2 * BCN) : nullptr;

    proj_kernel<<<dim3(Nx / 128, Bx, 3), 512>>>(x, Wk, bk, Wq, bq, Wv, bv);
    attn_kernel<<<dim3(Nx / 128, Bx), 256>>>();
    oproj_kernel<<<dim3(Nx / 128, Bx), 512>>>(x, Wo, bo, out_y, out_o, out_g);
}

// round 3
// speedup vs baseline: 1.8061x; 1.3320x over previous
#include <cuda_runtime.h>

#define Bx 4
#define Cx 256
#define Nx 4096
#define Ex 32
#define TK 128

// Scratch (allocation-free rule: __device__ globals). 8 MB total.
__device__ float g_f[Bx * Ex * Nx];
__device__ float g_g[Bx * Ex * Nx];
__device__ float g_h[Bx * Ex * Nx];
__device__ float g_v[Bx * Ex * Nx];

// ---------------------------------------------------------------------------
// Kernel 1: f/g/h = W @ x + b.
// grid (32, B, 3), block 128. Thread = (token-lane 0..31 [x4 tokens], e-slice
// 0..3 [8 outputs]). 4 tokens per thread via float4 -> 128 FFMA per 12 LDG.
// es is warp-uniform so W loads are broadcast.
// ---------------------------------------------------------------------------
__global__ __launch_bounds__(128) void proj_kernel(
    const float* __restrict__ x,
    const float* __restrict__ Wk, const float* __restrict__ bk,
    const float* __restrict__ Wq, const float* __restrict__ bq,
    const float* __restrict__ Wv, const float* __restrict__ bv)
{
    const int tid = threadIdx.x;
    const int tl  = tid & 31;           // token-lane
    const int es  = tid >> 5;           // e-slice 0..3 (warp-uniform)
    const int n0  = blockIdx.x * 128 + tl * 4;
    const int b   = blockIdx.y;
    const int z   = blockIdx.z;

    const float* W;
    const float* bias;
    float* out;
    if (z == 0)      { W = Wk; bias = bk; out = g_f; }
    else if (z == 1) { W = Wq; bias = bq; out = g_g; }
    else             { W = Wv; bias = bv; out = g_h; }

    const float* xp = x + (size_t)b * Cx * Nx + n0;
    const int e0 = es * 8;

    float acc[8][4];
#pragma unroll
    for (int e = 0; e < 8; e++) {
        const float bv0 = bias[e0 + e];
#pragma unroll
        for (int t = 0; t < 4; t++) acc[e][t] = bv0;
    }

    const float4* W4 = (const float4*)W;  // [Ex][Cx/4]
    for (int c4 = 0; c4 < Cx / 4; c4++) {
        float4 xv[4];
#pragma unroll
        for (int j = 0; j < 4; j++)
            xv[j] = *(const float4*)&xp[(c4 * 4 + j) * Nx];
#pragma unroll
        for (int e = 0; e < 8; e++) {
            const float4 w = W4[(e0 + e) * (Cx / 4) + c4];
            acc[e][0] += w.x * xv[0].x + w.y * xv[1].x + w.z * xv[2].x + w.w * xv[3].x;
            acc[e][1] += w.x * xv[0].y + w.y * xv[1].y + w.z * xv[2].y + w.w * xv[3].y;
            acc[e][2] += w.x * xv[0].z + w.y * xv[1].z + w.z * xv[2].z + w.w * xv[3].z;
            acc[e][3] += w.x * xv[0].w + w.y * xv[1].w + w.z * xv[2].w + w.w * xv[3].w;
        }
    }

    float* op = out + (size_t)b * Ex * Nx + n0;
#pragma unroll
    for (int e = 0; e < 8; e++)
        *(float4*)&op[(e0 + e) * Nx] =
            make_float4(acc[e][0], acc[e][1], acc[e][2], acc[e][3]);
}

// ---------------------------------------------------------------------------
// Kernel 2: fused attention. grid (64, B) = 256 blocks, block 256.
// 64 queries/block; threads split each 128-key tile 4-way (32 keys each).
// g pre-scaled by log2(e) so p = exp2f(s) (bare EX2, softmax-ratio exact).
// Partials combined through smem (reusing the tile storage).
// No online-max: scores ~ N(0,32) -> exp2 never overflows fp32.
// ---------------------------------------------------------------------------
__global__ __launch_bounds__(256) void attn_kernel()
{
    __shared__ float tile[2][Ex][TK];   // [0]=f, [1]=h : 32 KB
    float (*f_s)[TK] = tile[0];
    float (*h_s)[TK] = tile[1];

    const int tid  = threadIdx.x;
    const int lane = tid & 63;          // query within block
    const int ks   = tid >> 6;          // key-quarter 0..3
    const int q    = blockIdx.x * 64 + lane;
    const int b    = blockIdx.y;

    const float* fb = g_f + (size_t)b * Ex * Nx;
    const float* gb = g_g + (size_t)b * Ex * Nx;
    const float* hb = g_h + (size_t)b * Ex * Nx;

    const float LOG2E = 1.4426950408889634f;
    float greg[Ex];
#pragma unroll
    for (int e = 0; e < Ex; e++) greg[e] = gb[e * Nx + q] * LOG2E;

    float acc[Ex];
#pragma unroll
    for (int e = 0; e < Ex; e++) acc[e] = 0.f;
    float l = 0.f;

    const int kbeg = ks * 32;

    for (int i0 = 0; i0 < Nx; i0 += TK) {
        __syncthreads();
        // vectorized tile fill: 1024 float4 per array, 4 per thread, coalesced
#pragma unroll
        for (int r = 0; r < 4; r++) {
            const int idx = r * 256 + tid;      // 0..1023
            const int e  = idx >> 5;            // / 32
            const int k4 = (idx & 31) * 4;
            *(float4*)&f_s[e][k4] = *(const float4*)&fb[e * Nx + i0 + k4];
            *(float4*)&h_s[e][k4] = *(const float4*)&hb[e * Nx + i0 + k4];
        }
        __syncthreads();

#pragma unroll 2
        for (int kk = 0; kk < 32; kk += 4) {
            const int k = kbeg + kk;
            float s0 = 0.f, s1 = 0.f, s2 = 0.f, s3 = 0.f;
#pragma unroll
            for (int e = 0; e < Ex; e++) {
                const float4 fv = *(const float4*)&f_s[e][k];  // broadcast LDS.128
                const float gv = greg[e];
                s0 += fv.x * gv; s1 += fv.y * gv;
                s2 += fv.z * gv; s3 += fv.w * gv;
            }
            const float p0 = exp2f(s0);
            const float p1 = exp2f(s1);
            const float p2 = exp2f(s2);
            const float p3 = exp2f(s3);
            l += (p0 + p1) + (p2 + p3);
#pragma unroll
            for (int e = 0; e < Ex; e++) {
                const float4 hv = *(const float4*)&h_s[e][k];
                acc[e] += hv.x * p0 + hv.y * p1 + hv.z * p2 + hv.w * p3;
            }
        }
    }

    // combine the four key-quarters through smem (reuse tile storage)
    __syncthreads();
    float* buf = &tile[0][0][0];        // need 3*64*33 = 6336 floats (<= 8192)
    if (ks != 0) {
        float* dst = buf + ((ks - 1) * 64 + lane) * 33;
#pragma unroll
        for (int e = 0; e < Ex; e++) dst[e] = acc[e];
        dst[32] = l;
    }
    __syncthreads();
    if (ks == 0) {
#pragma unroll
        for (int p = 0; p < 3; p++) {
            const float* src = buf + (p * 64 + lane) * 33;
#pragma unroll
            for (int e = 0; e < Ex; e++) acc[e] += src[e];
            l += src[32];
        }
        const float inv = 1.0f / l;
        float* vp = g_v + (size_t)b * Ex * Nx + q;
#pragma unroll
        for (int e = 0; e < Ex; e++) vp[e * Nx] = acc[e] * inv;
    }
}

// ---------------------------------------------------------------------------
// Kernel 3: o = Wo @ v + bo ; y = 0.5*o + x ; gamma = 0.5
// grid (32, B), block 256. Thread = (token-lane 0..63 [x2 tokens],
// channel-slice 0..3 [64 channels]).
// ---------------------------------------------------------------------------
__global__ __launch_bounds__(256) void oproj_kernel(
    const float* __restrict__ x,
    const float* __restrict__ Wo, const float* __restrict__ bo,
    float* __restrict__ out_y, float* __restrict__ out_o,
    float* __restrict__ out_gamma)
{
    const int tid = threadIdx.x;
    const int tl  = tid & 63;
    const int cs  = tid >> 6;           // channel-slice 0..3 (warp-uniform)
    const int n0  = blockIdx.x * 128 + tl * 2;
    const int b   = blockIdx.y;

    float2 vr[Ex];
    const float* vp = g_v + (size_t)b * Ex * Nx + n0;
#pragma unroll
    for (int e = 0; e < Ex; e++) vr[e] = *(const float2*)&vp[e * Nx];

    const float4* Wo4 = (const float4*)Wo;  // [Cx][Ex/4]
    const float* xp = x + (size_t)b * Cx * Nx + n0;
    float* yp = out_y + (size_t)b * Cx * Nx + n0;
    float* op = out_o ? (out_o + (size_t)b * Cx * Nx + n0) : nullptr;

    const int c0 = cs * 64;
#pragma unroll 4
    for (int ci = 0; ci < 64; ci++) {
        const int c = c0 + ci;
        float a0 = bo[c], a1 = a0;
#pragma unroll
        for (int e4 = 0; e4 < Ex / 4; e4++) {
            const float4 w = Wo4[c * (Ex / 4) + e4];
            a0 += w.x * vr[e4*4+0].x + w.y * vr[e4*4+1].x +
                  w.z * vr[e4*4+2].x + w.w * vr[e4*4+3].x;
            a1 += w.x * vr[e4*4+0].y + w.y * vr[e4*4+1].y +
                  w.z * vr[e4*4+2].y + w.w * vr[e4*4+3].y;
        }
        if (op) *(float2*)&op[c * Nx] = make_float2(a0, a1);
        const float2 xv = *(const float2*)&xp[c * Nx];
        *(float2*)&yp[c * Nx] = make_float2(0.5f * a0 + xv.x, 0.5f * a1 + xv.y);
    }

    if (out_gamma && blockIdx.x == 0 && blockIdx.y == 0 && threadIdx.x == 0)
        out_gamma[0] = 0.5f;
}

// ---------------------------------------------------------------------------
extern "C" void kernel_launch(void* const* d_in, const int* in_sizes, int n_in,
                              void* d_out, int out_size)
{
    const float* x  = (const float*)d_in[0];
    const float* Wk = (const float*)d_in[1];
    const float* bk = (const float*)d_in[2];
    const float* Wq = (const float*)d_in[3];
    const float* bq = (const float*)d_in[4];
    const float* Wv = (const float*)d_in[5];
    const float* bv = (const float*)d_in[6];
    const float* Wo = (const float*)d_in[7];
    const float* bo = (const float*)d_in[8];

    const size_t BCN = (size_t)Bx * Cx * Nx;  // 4194304
    float* out = (float*)d_out;

    const bool full = ((size_t)out_size >= 2 * BCN + 1);
    float* out_y = out;
    float* out_o = full ? (out + BCN) : nullptr;
    float* out_g = full ? (out + 2 * BCN) : nullptr;

    proj_kernel<<<dim3(Nx / 128, Bx, 3), 128>>>(x, Wk, bk, Wq, bq, Wv, bv);
    attn_kernel<<<dim3(Nx / 64, Bx), 256>>>();
    oproj_kernel<<<dim3(Nx / 128, Bx), 256>>>(x, Wo, bo, out_y, out_o, out_g);
}

// round 4
// speedup vs baseline: 3.4489x; 1.9095x over previous
#include <cuda_runtime.h>
#include <cuda_bf16.h>
#include <cstdint>

#define Bx 4
#define Cx 256
#define Nx 4096
#define Ex 32
#define TK 128

// Scratch (allocation-free rule: __device__ globals).
__device__ float g_f[Bx * Ex * Nx];
__device__ float g_g[Bx * Ex * Nx];
__device__ float g_h[Bx * Ex * Nx];
__device__ float g_v[Bx * Ex * Nx];

// ---------------------------------------------------------------------------
// mma.sync.m16n8k16 bf16, f32 accumulate (A row-major, B col-major)
// ---------------------------------------------------------------------------
__device__ __forceinline__ void mma16816(float* c, const uint32_t* a,
                                         uint32_t b0, uint32_t b1)
{
    asm volatile(
        "mma.sync.aligned.m16n8k16.row.col.f32.bf16.bf16.f32 "
        "{%0,%1,%2,%3},{%4,%5,%6,%7},{%8,%9},{%0,%1,%2,%3};\n"
        : "+f"(c[0]), "+f"(c[1]), "+f"(c[2]), "+f"(c[3])
        : "r"(a[0]), "r"(a[1]), "r"(a[2]), "r"(a[3]), "r"(b0), "r"(b1));
}

__device__ __forceinline__ float ex2(float x)
{
    float y;
    asm("ex2.approx.ftz.f32 %0, %1;" : "=f"(y) : "f"(x));
    return y;
}

__device__ __forceinline__ uint32_t packbf(float lo, float hi)
{
    __nv_bfloat162 t = __float22bfloat162_rn(make_float2(lo, hi));
    return *(uint32_t*)&t;
}

// ---------------------------------------------------------------------------
// Kernel 1: f/g/h = W @ x + b.  grid (32, B, 3), block 256.
// Thread = (token-lane 0..31 [x4 tokens], e-slice 0..7 [4 outputs each]).
// ---------------------------------------------------------------------------
__global__ __launch_bounds__(256) void proj_kernel(
    const float* __restrict__ x,
    const float* __restrict__ Wk, const float* __restrict__ bk,
    const float* __restrict__ Wq, const float* __restrict__ bq,
    const float* __restrict__ Wv, const float* __restrict__ bv)
{
    const int tid = threadIdx.x;
    const int tl  = tid & 31;
    const int es  = tid >> 5;           // 0..7, warp-uniform
    const int n0  = blockIdx.x * 128 + tl * 4;
    const int b   = blockIdx.y;
    const int z   = blockIdx.z;

    const float* W;
    const float* bias;
    float* out;
    if (z == 0)      { W = Wk; bias = bk; out = g_f; }
    else if (z == 1) { W = Wq; bias = bq; out = g_g; }
    else             { W = Wv; bias = bv; out = g_h; }

    const float* xp = x + (size_t)b * Cx * Nx + n0;
    const int e0 = es * 4;

    float acc[4][4];
#pragma unroll
    for (int e = 0; e < 4; e++) {
        const float bv0 = bias[e0 + e];
#pragma unroll
        for (int t = 0; t < 4; t++) acc[e][t] = bv0;
    }

    const float4* W4 = (const float4*)W;  // [Ex][Cx/4]
    for (int c4 = 0; c4 < Cx / 4; c4++) {
        float4 xv[4];
#pragma unroll
        for (int j = 0; j < 4; j++)
            xv[j] = *(const float4*)&xp[(c4 * 4 + j) * Nx];
#pragma unroll
        for (int e = 0; e < 4; e++) {
            const float4 w = W4[(e0 + e) * (Cx / 4) + c4];
            acc[e][0] += w.x * xv[0].x + w.y * xv[1].x + w.z * xv[2].x + w.w * xv[3].x;
            acc[e][1] += w.x * xv[0].y + w.y * xv[1].y + w.z * xv[2].y + w.w * xv[3].y;
            acc[e][2] += w.x * xv[0].z + w.y * xv[1].z + w.z * xv[2].z + w.w * xv[3].z;
            acc[e][3] += w.x * xv[0].w + w.y * xv[1].w + w.z * xv[2].w + w.w * xv[3].w;
        }
    }

    float* op = out + (size_t)b * Ex * Nx + n0;
#pragma unroll
    for (int e = 0; e < 4; e++)
        *(float4*)&op[(e0 + e) * Nx] =
            make_float4(acc[e][0], acc[e][1], acc[e][2], acc[e][3]);
}

// ---------------------------------------------------------------------------
// Kernel 2: tensor-core flash attention. grid (32, B), block 256 (8 warps).
// Warp w owns queries [blk*128 + w*16, +16). Loop over 128-key tiles:
//   S'[16q x 128k] = (log2e * G)^T F      (bf16 hi/lo 3-term split, f32 acc)
//   P = exp2(S'), l += rowsum(P)
//   V^T[16q x 32e] += P * H^T             (bf16 hi/lo 3-term split)
// C-fragment of S' re-packs directly into A-fragment of the PV mma.
// Smem: f transposed [k][e] (row 40 bf16), h natural [e][k] (row 136 bf16).
// ---------------------------------------------------------------------------
#define FPAD 40
#define HPAD 136

__global__ __launch_bounds__(256) void attn_mma_kernel()
{
    __shared__ __align__(16) __nv_bfloat16 fh[TK][FPAD];
    __shared__ __align__(16) __nv_bfloat16 fl[TK][FPAD];
    __shared__ __align__(16) __nv_bfloat16 hh[Ex][HPAD];
    __shared__ __align__(16) __nv_bfloat16 hl[Ex][HPAD];

    const int tid  = threadIdx.x;
    const int warp = tid >> 5;
    const int lane = tid & 31;
    const int b    = blockIdx.y;
    const int qw   = blockIdx.x * 128 + warp * 16;   // warp's query base

    const float* fb = g_f + (size_t)b * Ex * Nx;
    const float* gb = g_g + (size_t)b * Ex * Nx;
    const float* hb = g_h + (size_t)b * Ex * Nx;

    const float LOG2E = 1.4426950408889634f;

    // ---- loop-invariant A-fragments from G (scaled by log2e, hi/lo split)
    uint32_t gAh[2][4], gAl[2][4];
    {
        const int qa = qw + (lane >> 2);
#pragma unroll
        for (int ke = 0; ke < 2; ke++) {
#pragma unroll
            for (int r = 0; r < 4; r++) {
                const int row = qa + (r & 1) * 8;
                const int e   = ke * 16 + (r >> 1) * 8 + (lane & 3) * 2;
                const float v0 = gb[e * Nx + row] * LOG2E;
                const float v1 = gb[(e + 1) * Nx + row] * LOG2E;
                const __nv_bfloat162 hi2 = __float22bfloat162_rn(make_float2(v0, v1));
                gAh[ke][r] = *(const uint32_t*)&hi2;
                const float l0 = v0 - __bfloat162float(hi2.x);
                const float l1 = v1 - __bfloat162float(hi2.y);
                gAl[ke][r] = packbf(l0, l1);
            }
        }
    }

    float Vac[4][4];
#pragma unroll
    for (int nt = 0; nt < 4; nt++)
#pragma unroll
        for (int r = 0; r < 4; r++) Vac[nt][r] = 0.f;
    float lsum0 = 0.f, lsum1 = 0.f;

    const uint32_t* fh32 = (const uint32_t*)&fh[0][0];  // row = FPAD/2 = 20 words
    const uint32_t* fl32 = (const uint32_t*)&fl[0][0];
    const uint32_t* hh32 = (const uint32_t*)&hh[0][0];  // row = HPAD/2 = 68 words
    const uint32_t* hl32 = (const uint32_t*)&hl[0][0];

    for (int i0 = 0; i0 < Nx; i0 += TK) {
        __syncthreads();
        // fill f transposed [k][e] (scalar, coalesced global reads)
#pragma unroll
        for (int it = 0; it < 16; it++) {
            const int idx = it * 256 + tid;
            const int k = idx & 127, e = idx >> 7;
            const float v = fb[e * Nx + i0 + k];
            const __nv_bfloat16 hi = __float2bfloat16_rn(v);
            fh[k][e] = hi;
            fl[k][e] = __float2bfloat16_rn(v - __bfloat162float(hi));
        }
        // fill h natural [e][k] (float2 reads, b32 smem stores)
#pragma unroll
        for (int it = 0; it < 8; it++) {
            const int idx = it * 256 + tid;
            const int k2 = (idx & 63) * 2, e = idx >> 6;
            const float2 v = *(const float2*)&hb[e * Nx + i0 + k2];
            const __nv_bfloat162 hi2 = __float22bfloat162_rn(make_float2(v.x, v.y));
            *(__nv_bfloat162*)&hh[e][k2] = hi2;
            const float l0 = v.x - __bfloat162float(hi2.x);
            const float l1 = v.y - __bfloat162float(hi2.y);
            const __nv_bfloat162 lo2 = __float22bfloat162_rn(make_float2(l0, l1));
            *(__nv_bfloat162*)&hl[e][k2] = lo2;
        }
        __syncthreads();

#pragma unroll 1
        for (int kk = 0; kk < 8; kk++) {      // 16 keys per step
            float c0[4] = {0.f, 0.f, 0.f, 0.f};
            float c1[4] = {0.f, 0.f, 0.f, 0.f};
            const int key0 = kk * 16 + (lane >> 2);

            // S' : 3-term split, 2 e-ksteps, 2 key n-tiles
#pragma unroll
            for (int ke = 0; ke < 2; ke++) {
                const int wo = ke * 8 + (lane & 3);
                const uint32_t bh00 = fh32[key0 * 20 + wo];
                const uint32_t bh01 = fh32[key0 * 20 + wo + 4];
                const uint32_t bh10 = fh32[(key0 + 8) * 20 + wo];
                const uint32_t bh11 = fh32[(key0 + 8) * 20 + wo + 4];
                mma16816(c0, gAh[ke], bh00, bh01);
                mma16816(c1, gAh[ke], bh10, bh11);
                mma16816(c0, gAl[ke], bh00, bh01);
                mma16816(c1, gAl[ke], bh10, bh11);
                const uint32_t bl00 = fl32[key0 * 20 + wo];
                const uint32_t bl01 = fl32[key0 * 20 + wo + 4];
                const uint32_t bl10 = fl32[(key0 + 8) * 20 + wo];
                const uint32_t bl11 = fl32[(key0 + 8) * 20 + wo + 4];
                mma16816(c0, gAh[ke], bl00, bl01);
                mma16816(c1, gAh[ke], bl10, bl11);
            }

            // exp2 + row-sum
            float p0[4], p1[4];
#pragma unroll
            for (int r = 0; r < 4; r++) { p0[r] = ex2(c0[r]); p1[r] = ex2(c1[r]); }
            lsum0 += (p0[0] + p0[1]) + (p1[0] + p1[1]);
            lsum1 += (p0[2] + p0[3]) + (p1[2] + p1[3]);

            // pack P into A-fragments (hi/lo)
            uint32_t aPh[4], aPl[4];
            {
                const __nv_bfloat162 t0 = __float22bfloat162_rn(make_float2(p0[0], p0[1]));
                const __nv_bfloat162 t1 = __float22bfloat162_rn(make_float2(p0[2], p0[3]));
                const __nv_bfloat162 t2 = __float22bfloat162_rn(make_float2(p1[0], p1[1]));
                const __nv_bfloat162 t3 = __float22bfloat162_rn(make_float2(p1[2], p1[3]));
                aPh[0] = *(const uint32_t*)&t0;
                aPh[1] = *(const uint32_t*)&t1;
                aPh[2] = *(const uint32_t*)&t2;
                aPh[3] = *(const uint32_t*)&t3;
                aPl[0] = packbf(p0[0] - __bfloat162float(t0.x), p0[1] - __bfloat162float(t0.y));
                aPl[1] = packbf(p0[2] - __bfloat162float(t1.x), p0[3] - __bfloat162float(t1.y));
                aPl[2] = packbf(p1[0] - __bfloat162float(t2.x), p1[1] - __bfloat162float(t2.y));
                aPl[3] = packbf(p1[2] - __bfloat162float(t3.x), p1[3] - __bfloat162float(t3.y));
            }

            // PV : V^T[16q x 32e] accumulate, K-step = these 16 keys
            const int kb2 = kk * 8 + (lane & 3);
#pragma unroll
            for (int nt = 0; nt < 4; nt++) {
                const int ew = (nt * 8 + (lane >> 2)) * 68 + kb2;
                const uint32_t b0 = hh32[ew];
                const uint32_t b1 = hh32[ew + 4];
                mma16816(Vac[nt], aPh, b0, b1);
                mma16816(Vac[nt], aPl, b0, b1);
                const uint32_t d0 = hl32[ew];
                const uint32_t d1 = hl32[ew + 4];
                mma16816(Vac[nt], aPh, d0, d1);
            }
        }
    }

    // reduce l over the quad (lanes sharing the same C rows)
    lsum0 += __shfl_xor_sync(0xffffffffu, lsum0, 1);
    lsum0 += __shfl_xor_sync(0xffffffffu, lsum0, 2);
    lsum1 += __shfl_xor_sync(0xffffffffu, lsum1, 1);
    lsum1 += __shfl_xor_sync(0xffffffffu, lsum1, 2);
    const float inv0 = 1.0f / lsum0;
    const float inv1 = 1.0f / lsum1;

    float* vp = g_v + (size_t)b * Ex * Nx;
    const int q0 = qw + (lane >> 2);
#pragma unroll
    for (int nt = 0; nt < 4; nt++) {
        const int e = nt * 8 + (lane & 3) * 2;
        vp[e * Nx + q0]           = Vac[nt][0] * inv0;
        vp[(e + 1) * Nx + q0]     = Vac[nt][1] * inv0;
        vp[e * Nx + q0 + 8]       = Vac[nt][2] * inv1;
        vp[(e + 1) * Nx + q0 + 8] = Vac[nt][3] * inv1;
    }
}

// ---------------------------------------------------------------------------
// Kernel 3: o = Wo @ v + bo ; y = 0.5*o + x ; gamma = 0.5
// ---------------------------------------------------------------------------
__global__ __launch_bounds__(256) void oproj_kernel(
    const float* __restrict__ x,
    const float* __restrict__ Wo, const float* __restrict__ bo,
    float* __restrict__ out_y, float* __restrict__ out_o,
    float* __restrict__ out_gamma)
{
    const int tid = threadIdx.x;
    const int tl  = tid & 63;
    const int cs  = tid >> 6;           // channel-slice 0..3 (warp-uniform)
    const int n0  = blockIdx.x * 128 + tl * 2;
    const int b   = blockIdx.y;

    float2 vr[Ex];
    const float* vp = g_v + (size_t)b * Ex * Nx + n0;
#pragma unroll
    for (int e = 0; e < Ex; e++) vr[e] = *(const float2*)&vp[e * Nx];

    const float4* Wo4 = (const float4*)Wo;  // [Cx][Ex/4]
    const float* xp = x + (size_t)b * Cx * Nx + n0;
    float* yp = out_y + (size_t)b * Cx * Nx + n0;
    float* op = out_o ? (out_o + (size_t)b * Cx * Nx + n0) : nullptr;

    const int c0 = cs * 64;
#pragma unroll 4
    for (int ci = 0; ci < 64; ci++) {
        const int c = c0 + ci;
        float a0 = bo[c], a1 = a0;
#pragma unroll
        for (int e4 = 0; e4 < Ex / 4; e4++) {
            const float4 w = Wo4[c * (Ex / 4) + e4];
            a0 += w.x * vr[e4*4+0].x + w.y * vr[e4*4+1].x +
                  w.z * vr[e4*4+2].x + w.w * vr[e4*4+3].x;
            a1 += w.x * vr[e4*4+0].y + w.y * vr[e4*4+1].y +
                  w.z * vr[e4*4+2].y + w.w * vr[e4*4+3].y;
        }
        if (op) *(float2*)&op[c * Nx] = make_float2(a0, a1);
        const float2 xv = *(const float2*)&xp[c * Nx];
        *(float2*)&yp[c * Nx] = make_float2(0.5f * a0 + xv.x, 0.5f * a1 + xv.y);
    }

    if (out_gamma && blockIdx.x == 0 && blockIdx.y == 0 && threadIdx.x == 0)
        out_gamma[0] = 0.5f;
}

// ---------------------------------------------------------------------------
extern "C" void kernel_launch(void* const* d_in, const int* in_sizes, int n_in,
                              void* d_out, int out_size)
{
    const float* x  = (const float*)d_in[0];
    const float* Wk = (const float*)d_in[1];
    const float* bk = (const float*)d_in[2];
    const float* Wq = (const float*)d_in[3];
    const float* bq = (const float*)d_in[4];
    const float* Wv = (const float*)d_in[5];
    const float* bv = (const float*)d_in[6];
    const float* Wo = (const float*)d_in[7];
    const float* bo = (const float*)d_in[8];

    const size_t BCN = (size_t)Bx * Cx * Nx;  // 4194304
    float* out = (float*)d_out;

    const bool full = ((size_t)out_size >= 2 * BCN + 1);
    float* out_y = out;
    float* out_o = full ? (out + BCN) : nullptr;
    float* out_g = full ? (out + 2 * BCN) : nullptr;

    proj_kernel<<<dim3(Nx / 128, Bx, 3), 256>>>(x, Wk, bk, Wq, bq, Wv, bv);
    attn_mma_kernel<<<dim3(Nx / 128, Bx), 256>>>();
    oproj_kernel<<<dim3(Nx / 128, Bx), 256>>>(x, Wo, bo, out_y, out_o, out_g);
}

// round 6
// speedup vs baseline: 3.7620x; 1.0908x over previous
#include <cuda_runtime.h>
#include <cuda_bf16.h>
#include <cstdint>

#define Bx 4
#define Cx 256
#define Nx 4096
#define Ex 32
#define TK 128

// Scratch (allocation-free rule: __device__ globals).
__device__ float g_g[Bx * Ex * Nx];
__device__ float g_v[Bx * Ex * Nx];
__device__ unsigned short g_f16h[(size_t)Bx * Nx * Ex];  // [b][n][e] hi
__device__ unsigned short g_f16l[(size_t)Bx * Nx * Ex];  // [b][n][e] lo
__device__ unsigned short g_h16h[(size_t)Bx * Ex * Nx];  // [b][e][n] hi
__device__ unsigned short g_h16l[(size_t)Bx * Ex * Nx];  // [b][e][n] lo

// ---------------------------------------------------------------------------
__device__ __forceinline__ void mma16816(float* c, const uint32_t* a,
                                         uint32_t b0, uint32_t b1)
{
    asm volatile(
        "mma.sync.aligned.m16n8k16.row.col.f32.bf16.bf16.f32 "
        "{%0,%1,%2,%3},{%4,%5,%6,%7},{%8,%9},{%0,%1,%2,%3};\n"
        : "+f"(c[0]), "+f"(c[1]), "+f"(c[2]), "+f"(c[3])
        : "r"(a[0]), "r"(a[1]), "r"(a[2]), "r"(a[3]), "r"(b0), "r"(b1));
}

__device__ __forceinline__ void ldsm4(uint32_t addr, uint32_t* r)
{
    asm volatile("ldmatrix.sync.aligned.m8n8.x4.shared.b16 {%0,%1,%2,%3}, [%4];"
                 : "=r"(r[0]), "=r"(r[1]), "=r"(r[2]), "=r"(r[3]) : "r"(addr));
}

__device__ __forceinline__ uint32_t smem_u32(const void* p)
{
    uint32_t a;
    asm("{ .reg .u64 t; cvta.to.shared.u64 t, %1; cvt.u32.u64 %0, t; }"
        : "=r"(a) : "l"(p));
    return a;
}

__device__ __forceinline__ float ex2(float x)
{
    float y;
    asm("ex2.approx.ftz.f32 %0, %1;" : "=f"(y) : "f"(x));
    return y;
}

__device__ __forceinline__ uint32_t packbf2(float a, float b)
{
    __nv_bfloat162 t = __float22bfloat162_rn(make_float2(a, b));
    return *(uint32_t*)&t;
}

// ===========================================================================
// Kernel 1: merged projections. grid (32, B), block 256.
// Thread = (token-lane 0..31 [x4 tokens], e-slice 0..7 [4 e each]).
// x loaded ONCE, used for all 3 projections (k/q/v).
// f -> bf16 hi/lo [b][n][32]; g -> float [b][e][n]; h -> bf16 hi/lo [b][e][n]
// ===========================================================================
__global__ __launch_bounds__(256) void proj_kernel(
    const float* __restrict__ x,
    const float* __restrict__ Wk, const float* __restrict__ bk,
    const float* __restrict__ Wq, const float* __restrict__ bq,
    const float* __restrict__ Wv, const float* __restrict__ bv)
{
    const int tid = threadIdx.x;
    const int tl  = tid & 31;
    const int es  = tid >> 5;           // 0..7, warp-uniform
    const int n0  = blockIdx.x * 128 + tl * 4;
    const int b   = blockIdx.y;
    const int e0  = es * 4;

    const float* xp = x + (size_t)b * Cx * Nx + n0;

    float acc[3][4][4];
#pragma unroll
    for (int e = 0; e < 4; e++) {
        const float b0v = bk[e0 + e], b1v = bq[e0 + e], b2v = bv[e0 + e];
#pragma unroll
        for (int t = 0; t < 4; t++) {
            acc[0][e][t] = b0v; acc[1][e][t] = b1v; acc[2][e][t] = b2v;
        }
    }

    const float4* Wk4 = (const float4*)Wk;
    const float4* Wq4 = (const float4*)Wq;
    const float4* Wv4 = (const float4*)Wv;

#pragma unroll 1
    for (int c4 = 0; c4 < Cx / 4; c4++) {
        float4 xv[4];
#pragma unroll
        for (int j = 0; j < 4; j++)
            xv[j] = *(const float4*)&xp[(c4 * 4 + j) * Nx];
#pragma unroll
        for (int e = 0; e < 4; e++) {
            const int wi = (e0 + e) * (Cx / 4) + c4;
            const float4 wk = Wk4[wi];
            const float4 wq = Wq4[wi];
            const float4 wv = Wv4[wi];
#pragma unroll
            for (int t = 0; t < 4; t++) {
                const float x0 = (&xv[0].x)[t];  // xv[j] component t
                // note: component extraction below done explicitly
            }
            acc[0][e][0] += wk.x*xv[0].x + wk.y*xv[1].x + wk.z*xv[2].x + wk.w*xv[3].x;
            acc[0][e][1] += wk.x*xv[0].y + wk.y*xv[1].y + wk.z*xv[2].y + wk.w*xv[3].y;
            acc[0][e][2] += wk.x*xv[0].z + wk.y*xv[1].z + wk.z*xv[2].z + wk.w*xv[3].z;
            acc[0][e][3] += wk.x*xv[0].w + wk.y*xv[1].w + wk.z*xv[2].w + wk.w*xv[3].w;
            acc[1][e][0] += wq.x*xv[0].x + wq.y*xv[1].x + wq.z*xv[2].x + wq.w*xv[3].x;
            acc[1][e][1] += wq.x*xv[0].y + wq.y*xv[1].y + wq.z*xv[2].y + wq.w*xv[3].y;
            acc[1][e][2] += wq.x*xv[0].z + wq.y*xv[1].z + wq.z*xv[2].z + wq.w*xv[3].z;
            acc[1][e][3] += wq.x*xv[0].w + wq.y*xv[1].w + wq.z*xv[2].w + wq.w*xv[3].w;
            acc[2][e][0] += wv.x*xv[0].x + wv.y*xv[1].x + wv.z*xv[2].x + wv.w*xv[3].x;
            acc[2][e][1] += wv.x*xv[0].y + wv.y*xv[1].y + wv.z*xv[2].y + wv.w*xv[3].y;
            acc[2][e][2] += wv.x*xv[0].z + wv.y*xv[1].z + wv.z*xv[2].z + wv.w*xv[3].z;
            acc[2][e][3] += wv.x*xv[0].w + wv.y*xv[1].w + wv.z*xv[2].w + wv.w*xv[3].w;
        }
    }

    // f (z=0): [b][n][32] bf16 hi/lo
#pragma unroll
    for (int t = 0; t < 4; t++) {
        const float v0 = acc[0][0][t], v1 = acc[0][1][t];
        const float v2 = acc[0][2][t], v3 = acc[0][3][t];
        const __nv_bfloat162 h01 = __float22bfloat162_rn(make_float2(v0, v1));
        const __nv_bfloat162 h23 = __float22bfloat162_rn(make_float2(v2, v3));
        const uint32_t l01 = packbf2(v0 - __bfloat162float(h01.x),
                                     v1 - __bfloat162float(h01.y));
        const uint32_t l23 = packbf2(v2 - __bfloat162float(h23.x),
                                     v3 - __bfloat162float(h23.y));
        const size_t base = ((size_t)b * Nx + (n0 + t)) * Ex + e0;
        *(uint2*)&g_f16h[base] = make_uint2(*(const uint32_t*)&h01,
                                            *(const uint32_t*)&h23);
        *(uint2*)&g_f16l[base] = make_uint2(l01, l23);
    }
    // g (z=1): float [b][e][n]
#pragma unroll
    for (int e = 0; e < 4; e++)
        *(float4*)&g_g[((size_t)b * Ex + e0 + e) * Nx + n0] =
            make_float4(acc[1][e][0], acc[1][e][1], acc[1][e][2], acc[1][e][3]);
    // h (z=2): [b][e][n] bf16 hi/lo
#pragma unroll
    for (int e = 0; e < 4; e++) {
        const float v0 = acc[2][e][0], v1 = acc[2][e][1];
        const float v2 = acc[2][e][2], v3 = acc[2][e][3];
        const __nv_bfloat162 h01 = __float22bfloat162_rn(make_float2(v0, v1));
        const __nv_bfloat162 h23 = __float22bfloat162_rn(make_float2(v2, v3));
        const uint32_t l01 = packbf2(v0 - __bfloat162float(h01.x),
                                     v1 - __bfloat162float(h01.y));
        const uint32_t l23 = packbf2(v2 - __bfloat162float(h23.x),
                                     v3 - __bfloat162float(h23.y));
        const size_t base = ((size_t)b * Ex + (e0 + e)) * Nx + n0;
        *(uint2*)&g_h16h[base] = make_uint2(*(const uint32_t*)&h01,
                                            *(const uint32_t*)&h23);
        *(uint2*)&g_h16l[base] = make_uint2(l01, l23);
    }
}

// ===========================================================================
// Kernel 2: mma.sync flash attention. grid (32, B), block 512 (16 warps).
// warp = (qt = w&7 -> 16 queries, kh = w>>3 -> 64-key half of each tile).
// Smem carve (38 KB static): fh[128][40]bf16 | fl | hh[32][136]bf16 | hl.
// Final combine of (Vac, l) across the two key-halves via smem.
// ===========================================================================
#define FROW 80     // bytes per fh row (40 bf16)
#define HROW 272    // bytes per hh row (136 bf16)

__global__ __launch_bounds__(512, 1) void attn_mma_kernel()
{
    __shared__ __align__(128) uint8_t S[38912];
    uint8_t* fhP = S;                 // 128*80   = 10240
    uint8_t* flP = S + 10240;        // 10240
    uint8_t* hhP = S + 20480;        // 32*272   = 8704
    uint8_t* hlP = S + 29184;        // 8704

    const int tid  = threadIdx.x;
    const int w    = tid >> 5;
    const int lane = tid & 31;
    const int qt   = w & 7;
    const int kh   = w >> 3;
    const int b    = blockIdx.y;
    const int qw   = blockIdx.x * 128 + qt * 16;

    const float* gb = g_g + (size_t)b * Ex * Nx;
    const unsigned short* fHg = g_f16h + (size_t)b * Nx * Ex;
    const unsigned short* fLg = g_f16l + (size_t)b * Nx * Ex;
    const unsigned short* hHg = g_h16h + (size_t)b * Ex * Nx;
    const unsigned short* hLg = g_h16l + (size_t)b * Ex * Nx;

    const uint32_t fhA = smem_u32(fhP);
    const uint32_t flA = smem_u32(flP);
    const uint32_t hhA = smem_u32(hhP);
    const uint32_t hlA = smem_u32(hlP);

    const float LOG2E = 1.4426950408889634f;

    // ---- loop-invariant A-fragments from G (scaled by log2e, hi/lo split)
    uint32_t gAh[2][4], gAl[2][4];
    {
        const int qa = qw + (lane >> 2);
#pragma unroll
        for (int ke = 0; ke < 2; ke++) {
#pragma unroll
            for (int r = 0; r < 4; r++) {
                const int row = qa + (r & 1) * 8;
                const int e   = ke * 16 + (r >> 1) * 8 + (lane & 3) * 2;
                const float v0 = gb[e * Nx + row] * LOG2E;
                const float v1 = gb[(e + 1) * Nx + row] * LOG2E;
                const __nv_bfloat162 hi2 = __float22bfloat162_rn(make_float2(v0, v1));
                gAh[ke][r] = *(const uint32_t*)&hi2;
                gAl[ke][r] = packbf2(v0 - __bfloat162float(hi2.x),
                                     v1 - __bfloat162float(hi2.y));
            }
        }
    }

    float Vac[4][4];
#pragma unroll
    for (int nt = 0; nt < 4; nt++)
#pragma unroll
        for (int r = 0; r < 4; r++) Vac[nt][r] = 0.f;
    float lsum0 = 0.f, lsum1 = 0.f;

    // ldmatrix lane-invariant address parts
    const int m      = lane >> 3;                    // matrix index 0..3
    const uint32_t fSel = (uint32_t)(((m >> 1) * 8 + (lane & 7)) * FROW + (m & 1) * 16);
    const uint32_t hSel = (uint32_t)(((m >> 1) * 8 + (lane & 7)) * HROW + (m & 1) * 16);

    for (int t = 0; t < Nx / TK; t++) {
        const int i0 = t * TK;
        __syncthreads();
        // fill F hi/lo: [k 128][e 32] bf16, row FROW. 512 thr: k=tid>>2, ch=tid&3
        {
            const int k = tid >> 2, ch = tid & 3;
            const size_t gsrc = (size_t)(i0 + k) * Ex + ch * 8;
            *(uint4*)(fhP + k * FROW + ch * 16) = *(const uint4*)(fHg + gsrc);
            *(uint4*)(flP + k * FROW + ch * 16) = *(const uint4*)(fLg + gsrc);
        }
        // fill H hi/lo: [e 32][k 128] bf16, row HROW. e=tid>>4, kc=(tid&15)*8
        {
            const int e = tid >> 4, kc = (tid & 15) * 8;
            const size_t gsrc = (size_t)e * Nx + i0 + kc;
            *(uint4*)(hhP + e * HROW + kc * 2) = *(const uint4*)(hHg + gsrc);
            *(uint4*)(hlP + e * HROW + kc * 2) = *(const uint4*)(hLg + gsrc);
        }
        __syncthreads();

#pragma unroll 1
        for (int kk = 0; kk < 4; kk++) {      // 16 keys per step, this key-half
            const uint32_t fTile = (uint32_t)((kh * 64 + kk * 16) * FROW) + fSel;
            float c0[4] = {0.f, 0.f, 0.f, 0.f};
            float c1[4] = {0.f, 0.f, 0.f, 0.f};

            // S' : 3-term split, 2 e-ksteps; B via ldmatrix.x4
#pragma unroll
            for (int ke = 0; ke < 2; ke++) {
                uint32_t bh[4], bl[4];
                ldsm4(fhA + fTile + ke * 32, bh);
                ldsm4(flA + fTile + ke * 32, bl);
                mma16816(c0, gAh[ke], bh[0], bh[1]);
                mma16816(c1, gAh[ke], bh[2], bh[3]);
                mma16816(c0, gAl[ke], bh[0], bh[1]);
                mma16816(c1, gAl[ke], bh[2], bh[3]);
                mma16816(c0, gAh[ke], bl[0], bl[1]);
                mma16816(c1, gAh[ke], bl[2], bl[3]);
            }

            // exp2 + row-sum
            float p0[4], p1[4];
#pragma unroll
            for (int r = 0; r < 4; r++) { p0[r] = ex2(c0[r]); p1[r] = ex2(c1[r]); }
            lsum0 += (p0[0] + p0[1]) + (p1[0] + p1[1]);
            lsum1 += (p0[2] + p0[3]) + (p1[2] + p1[3]);

            // pack P into A-fragments (hi/lo)
            uint32_t aPh[4], aPl[4];
            {
                const __nv_bfloat162 t0 = __float22bfloat162_rn(make_float2(p0[0], p0[1]));
                const __nv_bfloat162 t1 = __float22bfloat162_rn(make_float2(p0[2], p0[3]));
                const __nv_bfloat162 t2 = __float22bfloat162_rn(make_float2(p1[0], p1[1]));
                const __nv_bfloat162 t3 = __float22bfloat162_rn(make_float2(p1[2], p1[3]));
                aPh[0] = *(const uint32_t*)&t0;
                aPh[1] = *(const uint32_t*)&t1;
                aPh[2] = *(const uint32_t*)&t2;
                aPh[3] = *(const uint32_t*)&t3;
                aPl[0] = packbf2(p0[0] - __bfloat162float(t0.x), p0[1] - __bfloat162float(t0.y));
                aPl[1] = packbf2(p0[2] - __bfloat162float(t1.x), p0[3] - __bfloat162float(t1.y));
                aPl[2] = packbf2(p1[0] - __bfloat162float(t2.x), p1[1] - __bfloat162float(t2.y));
                aPl[3] = packbf2(p1[2] - __bfloat162float(t3.x), p1[3] - __bfloat162float(t3.y));
            }

            // PV : V^T[16q x 32e] accumulate; B via 4x ldmatrix.x4
            const uint32_t hTile = (uint32_t)(kh * 128 + kk * 32) + hSel;
            uint32_t b0[4], b1[4], d0[4], d1[4];
            ldsm4(hhA + hTile, b0);                 // e-rows 0..15  (nt 0,1)
            ldsm4(hhA + hTile + 16 * HROW, b1);     // e-rows 16..31 (nt 2,3)
            ldsm4(hlA + hTile, d0);
            ldsm4(hlA + hTile + 16 * HROW, d1);
#pragma unroll
            for (int j = 0; j < 2; j++) {
                mma16816(Vac[j],     aPh, b0[2*j], b0[2*j+1]);
                mma16816(Vac[j],     aPl, b0[2*j], b0[2*j+1]);
                mma16816(Vac[j],     aPh, d0[2*j], d0[2*j+1]);
                mma16816(Vac[2+j],   aPh, b1[2*j], b1[2*j+1]);
                mma16816(Vac[2+j],   aPl, b1[2*j], b1[2*j+1]);
                mma16816(Vac[2+j],   aPh, d1[2*j], d1[2*j+1]);
            }
        }
    }

    // ---- combine the two key-halves
    __syncthreads();
    float* Vbuf = (float*)S;               // [128][33] floats = 16896 B
    float* Lbuf = (float*)(S + 17408);     // 128 floats

    lsum0 += __shfl_xor_sync(0xffffffffu, lsum0, 1);
    lsum0 += __shfl_xor_sync(0xffffffffu, lsum0, 2);
    lsum1 += __shfl_xor_sync(0xffffffffu, lsum1, 1);
    lsum1 += __shfl_xor_sync(0xffffffffu, lsum1, 2);

    const int qrow = lane >> 2;
    if (kh == 1) {
#pragma unroll
        for (int nt = 0; nt < 4; nt++) {
            const int e = nt * 8 + (lane & 3) * 2;
            Vbuf[(qt * 16 + qrow) * 33 + e]           = Vac[nt][0];
            Vbuf[(qt * 16 + qrow) * 33 + e + 1]       = Vac[nt][1];
            Vbuf[(qt * 16 + qrow + 8) * 33 + e]       = Vac[nt][2];
            Vbuf[(qt * 16 + qrow + 8) * 33 + e + 1]   = Vac[nt][3];
        }
        if ((lane & 3) == 0) {
            Lbuf[qt * 16 + qrow]     = lsum0;
            Lbuf[qt * 16 + qrow + 8] = lsum1;
        }
    }
    __syncthreads();
    if (kh == 0) {
        const float inv0 = 1.0f / (lsum0 + Lbuf[qt * 16 + qrow]);
        const float inv1 = 1.0f / (lsum1 + Lbuf[qt * 16 + qrow + 8]);
        float* vp = g_v + (size_t)b * Ex * Nx;
        const int q0 = qw + qrow;
#pragma unroll
        for (int nt = 0; nt < 4; nt++) {
            const int e = nt * 8 + (lane & 3) * 2;
            vp[e * Nx + q0] =
                (Vac[nt][0] + Vbuf[(qt * 16 + qrow) * 33 + e]) * inv0;
            vp[(e + 1) * Nx + q0] =
                (Vac[nt][1] + Vbuf[(qt * 16 + qrow) * 33 + e + 1]) * inv0;
            vp[e * Nx + q0 + 8] =
                (Vac[nt][2] + Vbuf[(qt * 16 + qrow + 8) * 33 + e]) * inv1;
            vp[(e + 1) * Nx + q0 + 8] =
                (Vac[nt][3] + Vbuf[(qt * 16 + qrow + 8) * 33 + e + 1]) * inv1;
        }
    }
}

// ===========================================================================
// Kernel 3: o = Wo @ v + bo ; y = 0.5*o + x ; gamma = 0.5
// ===========================================================================
__global__ __launch_bounds__(256) void oproj_kernel(
    const float* __restrict__ x,
    const float* __restrict__ Wo, const float* __restrict__ bo,
    float* __restrict__ out_y, float* __restrict__ out_o,
    float* __restrict__ out_gamma)
{
    const int tid = threadIdx.x;
    const int tl  = tid & 63;
    const int cs  = tid >> 6;           // channel-slice 0..3 (warp-uniform)
    const int n0  = blockIdx.x * 128 + tl * 2;
    const int b   = blockIdx.y;

    float2 vr[Ex];
    const float* vp = g_v + (size_t)b * Ex * Nx + n0;
#pragma unroll
    for (int e = 0; e < Ex; e++) vr[e] = *(const float2*)&vp[e * Nx];

    const float4* Wo4 = (const float4*)Wo;  // [Cx][Ex/4]
    const float* xp = x + (size_t)b * Cx * Nx + n0;
    float* yp = out_y + (size_t)b * Cx * Nx + n0;
    float* op = out_o ? (out_o + (size_t)b * Cx * Nx + n0) : nullptr;

    const int c0 = cs * 64;
#pragma unroll 4
    for (int ci = 0; ci < 64; ci++) {
        const int c = c0 + ci;
        float a0 = bo[c], a1 = a0;
#pragma unroll
        for (int e4 = 0; e4 < Ex / 4; e4++) {
            const float4 w = Wo4[c * (Ex / 4) + e4];
            a0 += w.x * vr[e4*4+0].x + w.y * vr[e4*4+1].x +
                  w.z * vr[e4*4+2].x + w.w * vr[e4*4+3].x;
            a1 += w.x * vr[e4*4+0].y + w.y * vr[e4*4+1].y +
                  w.z * vr[e4*4+2].y + w.w * vr[e4*4+3].y;
        }
        if (op) *(float2*)&op[c * Nx] = make_float2(a0, a1);
        const float2 xv = *(const float2*)&xp[c * Nx];
        *(float2*)&yp[c * Nx] = make_float2(0.5f * a0 + xv.x, 0.5f * a1 + xv.y);
    }

    if (out_gamma && blockIdx.x == 0 && blockIdx.y == 0 && threadIdx.x == 0)
        out_gamma[0] = 0.5f;
}

// ===========================================================================
extern "C" void kernel_launch(void* const* d_in, const int* in_sizes, int n_in,
                              void* d_out, int out_size)
{
    const float* x  = (const float*)d_in[0];
    const float* Wk = (const float*)d_in[1];
    const float* bk = (const float*)d_in[2];
    const float* Wq = (const float*)d_in[3];
    const float* bq = (const float*)d_in[4];
    const float* Wv = (const float*)d_in[5];
    const float* bv = (const float*)d_in[6];
    const float* Wo = (const float*)d_in[7];
    const float* bo = (const float*)d_in[8];

    const size_t BCN = (size_t)Bx * Cx * Nx;  // 4194304
    float* out = (float*)d_out;

    const bool full = ((size_t)out_size >= 2 * BCN + 1);
    float* out_y = out;
    float* out_o = full ? (out + BCN) : nullptr;
    float* out_g = full ? (out + 2 * BCN) : nullptr;

    proj_kernel<<<dim3(Nx / 128, Bx), 256>>>(x, Wk, bk, Wq, bq, Wv, bv);
    attn_mma_kernel<<<dim3(Nx / 128, Bx), 512>>>();
    oproj_kernel<<<dim3(Nx / 128, Bx), 256>>>(x, Wo, bo, out_y, out_o, out_g);
}

// round 7
// speedup vs baseline: 4.8854x; 1.2986x over previous
#include <cuda_runtime.h>
#include <cuda_bf16.h>
#include <cstdint>

#define Bx 4
#define Cx 256
#define Nx 4096
#define Ex 32
#define TK 128

// Scratch (allocation-free rule: __device__ globals).
__device__ float g_g[Bx * Ex * Nx];
__device__ float g_v[Bx * Ex * Nx];
__device__ unsigned short g_f16h[(size_t)Bx * Nx * Ex];  // [b][n][e] hi
__device__ unsigned short g_f16l[(size_t)Bx * Nx * Ex];  // [b][n][e] lo
__device__ unsigned short g_h16h[(size_t)Bx * Ex * Nx];  // [b][e][n] hi
__device__ unsigned short g_h16l[(size_t)Bx * Ex * Nx];  // [b][e][n] lo

// ---------------------------------------------------------------------------
__device__ __forceinline__ void mma16816(float* c, const uint32_t* a,
                                         uint32_t b0, uint32_t b1)
{
    asm volatile(
        "mma.sync.aligned.m16n8k16.row.col.f32.bf16.bf16.f32 "
        "{%0,%1,%2,%3},{%4,%5,%6,%7},{%8,%9},{%0,%1,%2,%3};\n"
        : "+f"(c[0]), "+f"(c[1]), "+f"(c[2]), "+f"(c[3])
        : "r"(a[0]), "r"(a[1]), "r"(a[2]), "r"(a[3]), "r"(b0), "r"(b1));
}

__device__ __forceinline__ void ldsm4(uint32_t addr, uint32_t* r)
{
    asm volatile("ldmatrix.sync.aligned.m8n8.x4.shared.b16 {%0,%1,%2,%3}, [%4];"
                 : "=r"(r[0]), "=r"(r[1]), "=r"(r[2]), "=r"(r[3]) : "r"(addr));
}

__device__ __forceinline__ uint32_t smem_u32(const void* p)
{
    uint32_t a;
    asm("{ .reg .u64 t; cvta.to.shared.u64 t, %1; cvt.u32.u64 %0, t; }"
        : "=r"(a) : "l"(p));
    return a;
}

__device__ __forceinline__ float ex2(float x)
{
    float y;
    asm("ex2.approx.ftz.f32 %0, %1;" : "=f"(y) : "f"(x));
    return y;
}

__device__ __forceinline__ uint32_t packbf2(float a, float b)
{
    __nv_bfloat162 t = __float22bfloat162_rn(make_float2(a, b));
    return *(uint32_t*)&t;
}

// ===========================================================================
// Kernel 1: f/g/h = W @ x + b.  grid (32, B, 3), block 256.
// Thread = (token-lane 0..31 [x4 tokens], e-slice 0..7 [4 e each]).
// f -> bf16 hi/lo [b][n][32]; g -> float [b][e][n]; h -> bf16 hi/lo [b][e][n]
// (z-split grid: 384 blocks — measured-best proj parallelism.)
// ===========================================================================
__global__ __launch_bounds__(256) void proj_kernel(
    const float* __restrict__ x,
    const float* __restrict__ Wk, const float* __restrict__ bk,
    const float* __restrict__ Wq, const float* __restrict__ bq,
    const float* __restrict__ Wv, const float* __restrict__ bv)
{
    const int tid = threadIdx.x;
    const int tl  = tid & 31;
    const int es  = tid >> 5;           // 0..7, warp-uniform
    const int n0  = blockIdx.x * 128 + tl * 4;
    const int b   = blockIdx.y;
    const int z   = blockIdx.z;

    const float* W;
    const float* bias;
    if (z == 0)      { W = Wk; bias = bk; }
    else if (z == 1) { W = Wq; bias = bq; }
    else             { W = Wv; bias = bv; }

    const float* xp = x + (size_t)b * Cx * Nx + n0;
    const int e0 = es * 4;

    float acc[4][4];
#pragma unroll
    for (int e = 0; e < 4; e++) {
        const float bv0 = bias[e0 + e];
#pragma unroll
        for (int t = 0; t < 4; t++) acc[e][t] = bv0;
    }

    const float4* W4 = (const float4*)W;  // [Ex][Cx/4]
#pragma unroll 1
    for (int c4 = 0; c4 < Cx / 4; c4++) {
        float4 xv[4];
#pragma unroll
        for (int j = 0; j < 4; j++)
            xv[j] = *(const float4*)&xp[(c4 * 4 + j) * Nx];
#pragma unroll
        for (int e = 0; e < 4; e++) {
            const float4 w = W4[(e0 + e) * (Cx / 4) + c4];
            acc[e][0] += w.x * xv[0].x + w.y * xv[1].x + w.z * xv[2].x + w.w * xv[3].x;
            acc[e][1] += w.x * xv[0].y + w.y * xv[1].y + w.z * xv[2].y + w.w * xv[3].y;
            acc[e][2] += w.x * xv[0].z + w.y * xv[1].z + w.z * xv[2].z + w.w * xv[3].z;
            acc[e][3] += w.x * xv[0].w + w.y * xv[1].w + w.z * xv[2].w + w.w * xv[3].w;
        }
    }

    if (z == 1) {
        // g: float [b][e][n]
#pragma unroll
        for (int e = 0; e < 4; e++)
            *(float4*)&g_g[((size_t)b * Ex + e0 + e) * Nx + n0] =
                make_float4(acc[e][0], acc[e][1], acc[e][2], acc[e][3]);
    } else if (z == 0) {
        // f: [b][n][32] bf16 hi/lo
#pragma unroll
        for (int t = 0; t < 4; t++) {
            const float v0 = acc[0][t], v1 = acc[1][t];
            const float v2 = acc[2][t], v3 = acc[3][t];
            const __nv_bfloat162 h01 = __float22bfloat162_rn(make_float2(v0, v1));
            const __nv_bfloat162 h23 = __float22bfloat162_rn(make_float2(v2, v3));
            const uint32_t l01 = packbf2(v0 - __bfloat162float(h01.x),
                                         v1 - __bfloat162float(h01.y));
            const uint32_t l23 = packbf2(v2 - __bfloat162float(h23.x),
                                         v3 - __bfloat162float(h23.y));
            const size_t base = ((size_t)b * Nx + (n0 + t)) * Ex + e0;
            *(uint2*)&g_f16h[base] = make_uint2(*(const uint32_t*)&h01,
                                                *(const uint32_t*)&h23);
            *(uint2*)&g_f16l[base] = make_uint2(l01, l23);
        }
    } else {
        // h: [b][e][n] bf16 hi/lo
#pragma unroll
        for (int e = 0; e < 4; e++) {
            const float v0 = acc[e][0], v1 = acc[e][1];
            const float v2 = acc[e][2], v3 = acc[e][3];
            const __nv_bfloat162 h01 = __float22bfloat162_rn(make_float2(v0, v1));
            const __nv_bfloat162 h23 = __float22bfloat162_rn(make_float2(v2, v3));
            const uint32_t l01 = packbf2(v0 - __bfloat162float(h01.x),
                                         v1 - __bfloat162float(h01.y));
            const uint32_t l23 = packbf2(v2 - __bfloat162float(h23.x),
                                         v3 - __bfloat162float(h23.y));
            const size_t base = ((size_t)b * Ex + (e0 + e)) * Nx + n0;
            *(uint2*)&g_h16h[base] = make_uint2(*(const uint32_t*)&h01,
                                                *(const uint32_t*)&h23);
            *(uint2*)&g_h16l[base] = make_uint2(l01, l23);
        }
    }
}

// ===========================================================================
// Kernel 2: mma.sync flash attention. grid (32, B), block 512 (16 warps).
// warp = (qt = w&7 -> 16 queries, kh = w>>3 -> 64-key half of each tile).
// Smem carve (38 KB static): fh[128][40]bf16 | fl | hh[32][136]bf16 | hl.
// ===========================================================================
#define FROW 80     // bytes per fh row (40 bf16)
#define HROW 272    // bytes per hh row (136 bf16)

__global__ __launch_bounds__(512, 1) void attn_mma_kernel()
{
    __shared__ __align__(128) uint8_t S[38912];
    uint8_t* fhP = S;                 // 128*80   = 10240
    uint8_t* flP = S + 10240;        // 10240
    uint8_t* hhP = S + 20480;        // 32*272   = 8704
    uint8_t* hlP = S + 29184;        // 8704

    const int tid  = threadIdx.x;
    const int w    = tid >> 5;
    const int lane = tid & 31;
    const int qt   = w & 7;
    const int kh   = w >> 3;
    const int b    = blockIdx.y;
    const int qw   = blockIdx.x * 128 + qt * 16;

    const float* gb = g_g + (size_t)b * Ex * Nx;
    const unsigned short* fHg = g_f16h + (size_t)b * Nx * Ex;
    const unsigned short* fLg = g_f16l + (size_t)b * Nx * Ex;
    const unsigned short* hHg = g_h16h + (size_t)b * Ex * Nx;
    const unsigned short* hLg = g_h16l + (size_t)b * Ex * Nx;

    const uint32_t fhA = smem_u32(fhP);
    const uint32_t flA = smem_u32(flP);
    const uint32_t hhA = smem_u32(hhP);
    const uint32_t hlA = smem_u32(hlP);

    const float LOG2E = 1.4426950408889634f;

    uint32_t gAh[2][4], gAl[2][4];
    {
        const int qa = qw + (lane >> 2);
#pragma unroll
        for (int ke = 0; ke < 2; ke++) {
#pragma unroll
            for (int r = 0; r < 4; r++) {
                const int row = qa + (r & 1) * 8;
                const int e   = ke * 16 + (r >> 1) * 8 + (lane & 3) * 2;
                const float v0 = gb[e * Nx + row] * LOG2E;
                const float v1 = gb[(e + 1) * Nx + row] * LOG2E;
                const __nv_bfloat162 hi2 = __float22bfloat162_rn(make_float2(v0, v1));
                gAh[ke][r] = *(const uint32_t*)&hi2;
                gAl[ke][r] = packbf2(v0 - __bfloat162float(hi2.x),
                                     v1 - __bfloat162float(hi2.y));
            }
        }
    }

    float Vac[4][4];
#pragma unroll
    for (int nt = 0; nt < 4; nt++)
#pragma unroll
        for (int r = 0; r < 4; r++) Vac[nt][r] = 0.f;
    float lsum0 = 0.f, lsum1 = 0.f;

    const int m = lane >> 3;
    const uint32_t fSel = (uint32_t)(((m >> 1) * 8 + (lane & 7)) * FROW + (m & 1) * 16);
    const uint32_t hSel = (uint32_t)(((m >> 1) * 8 + (lane & 7)) * HROW + (m & 1) * 16);

    for (int t = 0; t < Nx / TK; t++) {
        const int i0 = t * TK;
        __syncthreads();
        {
            const int k = tid >> 2, ch = tid & 3;
            const size_t gsrc = (size_t)(i0 + k) * Ex + ch * 8;
            *(uint4*)(fhP + k * FROW + ch * 16) = *(const uint4*)(fHg + gsrc);
            *(uint4*)(flP + k * FROW + ch * 16) = *(const uint4*)(fLg + gsrc);
        }
        {
            const int e = tid >> 4, kc = (tid & 15) * 8;
            const size_t gsrc = (size_t)e * Nx + i0 + kc;
            *(uint4*)(hhP + e * HROW + kc * 2) = *(const uint4*)(hHg + gsrc);
            *(uint4*)(hlP + e * HROW + kc * 2) = *(const uint4*)(hLg + gsrc);
        }
        __syncthreads();

#pragma unroll 1
        for (int kk = 0; kk < 4; kk++) {
            const uint32_t fTile = (uint32_t)((kh * 64 + kk * 16) * FROW) + fSel;
            float c0[4] = {0.f, 0.f, 0.f, 0.f};
            float c1[4] = {0.f, 0.f, 0.f, 0.f};

#pragma unroll
            for (int ke = 0; ke < 2; ke++) {
                uint32_t bh[4], bl[4];
                ldsm4(fhA + fTile + ke * 32, bh);
                ldsm4(flA + fTile + ke * 32, bl);
                mma16816(c0, gAh[ke], bh[0], bh[1]);
                mma16816(c1, gAh[ke], bh[2], bh[3]);
                mma16816(c0, gAl[ke], bh[0], bh[1]);
                mma16816(c1, gAl[ke], bh[2], bh[3]);
                mma16816(c0, gAh[ke], bl[0], bl[1]);
                mma16816(c1, gAh[ke], bl[2], bl[3]);
            }

            float p0[4], p1[4];
#pragma unroll
            for (int r = 0; r < 4; r++) { p0[r] = ex2(c0[r]); p1[r] = ex2(c1[r]); }
            lsum0 += (p0[0] + p0[1]) + (p1[0] + p1[1]);
            lsum1 += (p0[2] + p0[3]) + (p1[2] + p1[3]);

            uint32_t aPh[4], aPl[4];
            {
                const __nv_bfloat162 t0 = __float22bfloat162_rn(make_float2(p0[0], p0[1]));
                const __nv_bfloat162 t1 = __float22bfloat162_rn(make_float2(p0[2], p0[3]));
                const __nv_bfloat162 t2 = __float22bfloat162_rn(make_float2(p1[0], p1[1]));
                const __nv_bfloat162 t3 = __float22bfloat162_rn(make_float2(p1[2], p1[3]));
                aPh[0] = *(const uint32_t*)&t0;
                aPh[1] = *(const uint32_t*)&t1;
                aPh[2] = *(const uint32_t*)&t2;
                aPh[3] = *(const uint32_t*)&t3;
                aPl[0] = packbf2(p0[0] - __bfloat162float(t0.x), p0[1] - __bfloat162float(t0.y));
                aPl[1] = packbf2(p0[2] - __bfloat162float(t1.x), p0[3] - __bfloat162float(t1.y));
                aPl[2] = packbf2(p1[0] - __bfloat162float(t2.x), p1[1] - __bfloat162float(t2.y));
                aPl[3] = packbf2(p1[2] - __bfloat162float(t3.x), p1[3] - __bfloat162float(t3.y));
            }

            const uint32_t hTile = (uint32_t)(kh * 128 + kk * 32) + hSel;
            uint32_t b0[4], b1[4], d0[4], d1[4];
            ldsm4(hhA + hTile, b0);
            ldsm4(hhA + hTile + 16 * HROW, b1);
            ldsm4(hlA + hTile, d0);
            ldsm4(hlA + hTile + 16 * HROW, d1);
#pragma unroll
            for (int j = 0; j < 2; j++) {
                mma16816(Vac[j],   aPh, b0[2*j], b0[2*j+1]);
                mma16816(Vac[j],   aPl, b0[2*j], b0[2*j+1]);
                mma16816(Vac[j],   aPh, d0[2*j], d0[2*j+1]);
                mma16816(Vac[2+j], aPh, b1[2*j], b1[2*j+1]);
                mma16816(Vac[2+j], aPl, b1[2*j], b1[2*j+1]);
                mma16816(Vac[2+j], aPh, d1[2*j], d1[2*j+1]);
            }
        }
    }

    __syncthreads();
    float* Vbuf = (float*)S;               // [128][33] floats
    float* Lbuf = (float*)(S + 17408);     // 128 floats

    lsum0 += __shfl_xor_sync(0xffffffffu, lsum0, 1);
    lsum0 += __shfl_xor_sync(0xffffffffu, lsum0, 2);
    lsum1 += __shfl_xor_sync(0xffffffffu, lsum1, 1);
    lsum1 += __shfl_xor_sync(0xffffffffu, lsum1, 2);

    const int qrow = lane >> 2;
    if (kh == 1) {
#pragma unroll
        for (int nt = 0; nt < 4; nt++) {
            const int e = nt * 8 + (lane & 3) * 2;
            Vbuf[(qt * 16 + qrow) * 33 + e]         = Vac[nt][0];
            Vbuf[(qt * 16 + qrow) * 33 + e + 1]     = Vac[nt][1];
            Vbuf[(qt * 16 + qrow + 8) * 33 + e]     = Vac[nt][2];
            Vbuf[(qt * 16 + qrow + 8) * 33 + e + 1] = Vac[nt][3];
        }
        if ((lane & 3) == 0) {
            Lbuf[qt * 16 + qrow]     = lsum0;
            Lbuf[qt * 16 + qrow + 8] = lsum1;
        }
    }
    __syncthreads();
    if (kh == 0) {
        const float inv0 = 1.0f / (lsum0 + Lbuf[qt * 16 + qrow]);
        const float inv1 = 1.0f / (lsum1 + Lbuf[qt * 16 + qrow + 8]);
        float* vp = g_v + (size_t)b * Ex * Nx;
        const int q0 = qw + qrow;
#pragma unroll
        for (int nt = 0; nt < 4; nt++) {
            const int e = nt * 8 + (lane & 3) * 2;
            vp[e * Nx + q0] =
                (Vac[nt][0] + Vbuf[(qt * 16 + qrow) * 33 + e]) * inv0;
            vp[(e + 1) * Nx + q0] =
                (Vac[nt][1] + Vbuf[(qt * 16 + qrow) * 33 + e + 1]) * inv0;
            vp[e * Nx + q0 + 8] =
                (Vac[nt][2] + Vbuf[(qt * 16 + qrow + 8) * 33 + e]) * inv1;
            vp[(e + 1) * Nx + q0 + 8] =
                (Vac[nt][3] + Vbuf[(qt * 16 + qrow + 8) * 33 + e + 1]) * inv1;
        }
    }
}

// ===========================================================================
// Kernel 3: o = Wo @ v + bo ; y = 0.5*o + x ; gamma = 0.5
// grid (64, B) = 256 blocks, block 256. Thread = (tl 0..31 [x2 tokens],
// cs 0..7 [32 channels]).
// ===========================================================================
__global__ __launch_bounds__(256) void oproj_kernel(
    const float* __restrict__ x,
    const float* __restrict__ Wo, const float* __restrict__ bo,
    float* __restrict__ out_y, float* __restrict__ out_o,
    float* __restrict__ out_gamma)
{
    const int tid = threadIdx.x;
    const int tl  = tid & 31;
    const int cs  = tid >> 5;           // 0..7, warp-uniform
    const int n0  = blockIdx.x * 64 + tl * 2;
    const int b   = blockIdx.y;

    float2 vr[Ex];
    const float* vp = g_v + (size_t)b * Ex * Nx + n0;
#pragma unroll
    for (int e = 0; e < Ex; e++) vr[e] = *(const float2*)&vp[e * Nx];

    const float4* Wo4 = (const float4*)Wo;  // [Cx][Ex/4]
    const float* xp = x + (size_t)b * Cx * Nx + n0;
    float* yp = out_y + (size_t)b * Cx * Nx + n0;
    float* op = out_o ? (out_o + (size_t)b * Cx * Nx + n0) : nullptr;

    const int c0 = cs * 32;
#pragma unroll 4
    for (int ci = 0; ci < 32; ci++) {
        const int c = c0 + ci;
        float a0 = bo[c], a1 = a0;
#pragma unroll
        for (int e4 = 0; e4 < Ex / 4; e4++) {
            const float4 w = Wo4[c * (Ex / 4) + e4];
            a0 += w.x * vr[e4*4+0].x + w.y * vr[e4*4+1].x +
                  w.z * vr[e4*4+2].x + w.w * vr[e4*4+3].x;
            a1 += w.x * vr[e4*4+0].y + w.y * vr[e4*4+1].y +
                  w.z * vr[e4*4+2].y + w.w * vr[e4*4+3].y;
        }
        if (op) *(float2*)&op[c * Nx] = make_float2(a0, a1);
        const float2 xv = *(const float2*)&xp[c * Nx];
        *(float2*)&yp[c * Nx] = make_float2(0.5f * a0 + xv.x, 0.5f * a1 + xv.y);
    }

    if (out_gamma && blockIdx.x == 0 && blockIdx.y == 0 && threadIdx.x == 0)
        out_gamma[0] = 0.5f;
}

// ===========================================================================
extern "C" void kernel_launch(void* const* d_in, const int* in_sizes, int n_in,
                              void* d_out, int out_size)
{
    const float* x  = (const float*)d_in[0];
    const float* Wk = (const float*)d_in[1];
    const float* bk = (const float*)d_in[2];
    const float* Wq = (const float*)d_in[3];
    const float* bq = (const float*)d_in[4];
    const float* Wv = (const float*)d_in[5];
    const float* bv = (const float*)d_in[6];
    const float* Wo = (const float*)d_in[7];
    const float* bo = (const float*)d_in[8];

    const size_t BCN = (size_t)Bx * Cx * Nx;  // 4194304
    float* out = (float*)d_out;

    const bool full = ((size_t)out_size >= 2 * BCN + 1);
    float* out_y = out;
    float* out_o = full ? (out + BCN) : nullptr;
    float* out_g = full ? (out + 2 * BCN) : nullptr;

    proj_kernel<<<dim3(Nx / 128, Bx, 3), 256>>>(x, Wk, bk, Wq, bq, Wv, bv);
    attn_mma_kernel<<<dim3(Nx / 128, Bx), 512>>>();
    oproj_kernel<<<dim3(Nx / 64, Bx), 256>>>(x, Wo, bo, out_y, out_o, out_g);
}

// round 8
// speedup vs baseline: 5.0197x; 1.0275x over previous
#include <cuda_runtime.h>
#include <cuda_bf16.h>
#include <cstdint>

#define Bx 4
#define Cx 256
#define Nx 4096
#define Ex 32
#define TK 128

// Scratch (allocation-free rule: __device__ globals).
__device__ float g_g[Bx * Ex * Nx];
__device__ float g_v[Bx * Ex * Nx];
__device__ unsigned short g_f16h[(size_t)Bx * Nx * Ex];  // [b][n][e] hi
__device__ unsigned short g_f16l[(size_t)Bx * Nx * Ex];  // [b][n][e] lo
__device__ unsigned short g_h16h[(size_t)Bx * Ex * Nx];  // [b][e][n] hi
__device__ unsigned short g_h16l[(size_t)Bx * Ex * Nx];  // [b][e][n] lo

// ---------------------------------------------------------------------------
__device__ __forceinline__ void mma16816(float* c, const uint32_t* a,
                                         uint32_t b0, uint32_t b1)
{
    asm volatile(
        "mma.sync.aligned.m16n8k16.row.col.f32.bf16.bf16.f32 "
        "{%0,%1,%2,%3},{%4,%5,%6,%7},{%8,%9},{%0,%1,%2,%3};\n"
        : "+f"(c[0]), "+f"(c[1]), "+f"(c[2]), "+f"(c[3])
        : "r"(a[0]), "r"(a[1]), "r"(a[2]), "r"(a[3]), "r"(b0), "r"(b1));
}

__device__ __forceinline__ void ldsm4(uint32_t addr, uint32_t* r)
{
    asm volatile("ldmatrix.sync.aligned.m8n8.x4.shared.b16 {%0,%1,%2,%3}, [%4];"
                 : "=r"(r[0]), "=r"(r[1]), "=r"(r[2]), "=r"(r[3]) : "r"(addr));
}

__device__ __forceinline__ uint32_t smem_u32(const void* p)
{
    uint32_t a;
    asm("{ .reg .u64 t; cvta.to.shared.u64 t, %1; cvt.u32.u64 %0, t; }"
        : "=r"(a) : "l"(p));
    return a;
}

__device__ __forceinline__ float ex2(float x)
{
    float y;
    asm("ex2.approx.ftz.f32 %0, %1;" : "=f"(y) : "f"(x));
    return y;
}

__device__ __forceinline__ uint32_t packbf2(float a, float b)
{
    __nv_bfloat162 t = __float22bfloat162_rn(make_float2(a, b));
    return *(uint32_t*)&t;
}

// ===========================================================================
// Kernel 1: f/g/h = W @ x + b.  grid (32, B, 3), block 256.
// Software-pipelined K loop: one-iteration x load-ahead (reg double buffer).
// ===========================================================================
__global__ __launch_bounds__(256) void proj_kernel(
    const float* __restrict__ x,
    const float* __restrict__ Wk, const float* __restrict__ bk,
    const float* __restrict__ Wq, const float* __restrict__ bq,
    const float* __restrict__ Wv, const float* __restrict__ bv)
{
    const int tid = threadIdx.x;
    const int tl  = tid & 31;
    const int es  = tid >> 5;           // 0..7, warp-uniform
    const int n0  = blockIdx.x * 128 + tl * 4;
    const int b   = blockIdx.y;
    const int z   = blockIdx.z;

    const float* W;
    const float* bias;
    if (z == 0)      { W = Wk; bias = bk; }
    else if (z == 1) { W = Wq; bias = bq; }
    else             { W = Wv; bias = bv; }

    const float* xp = x + (size_t)b * Cx * Nx + n0;
    const int e0 = es * 4;

    float acc[4][4];
#pragma unroll
    for (int e = 0; e < 4; e++) {
        const float bv0 = bias[e0 + e];
#pragma unroll
        for (int t = 0; t < 4; t++) acc[e][t] = bv0;
    }

    const float4* W4 = (const float4*)W;  // [Ex][Cx/4]

    float4 xa[4], xb[4];
#pragma unroll
    for (int j = 0; j < 4; j++)
        xa[j] = *(const float4*)&xp[j * Nx];

#pragma unroll 1
    for (int c4 = 0; c4 < Cx / 4; c4 += 2) {
        // prefetch c4+1
#pragma unroll
        for (int j = 0; j < 4; j++)
            xb[j] = *(const float4*)&xp[((c4 + 1) * 4 + j) * Nx];
        // compute with xa (c4)
#pragma unroll
        for (int e = 0; e < 4; e++) {
            const float4 w = W4[(e0 + e) * (Cx / 4) + c4];
            acc[e][0] += w.x * xa[0].x + w.y * xa[1].x + w.z * xa[2].x + w.w * xa[3].x;
            acc[e][1] += w.x * xa[0].y + w.y * xa[1].y + w.z * xa[2].y + w.w * xa[3].y;
            acc[e][2] += w.x * xa[0].z + w.y * xa[1].z + w.z * xa[2].z + w.w * xa[3].z;
            acc[e][3] += w.x * xa[0].w + w.y * xa[1].w + w.z * xa[2].w + w.w * xa[3].w;
        }
        // prefetch c4+2
        if (c4 + 2 < Cx / 4) {
#pragma unroll
            for (int j = 0; j < 4; j++)
                xa[j] = *(const float4*)&xp[((c4 + 2) * 4 + j) * Nx];
        }
        // compute with xb (c4+1)
#pragma unroll
        for (int e = 0; e < 4; e++) {
            const float4 w = W4[(e0 + e) * (Cx / 4) + c4 + 1];
            acc[e][0] += w.x * xb[0].x + w.y * xb[1].x + w.z * xb[2].x + w.w * xb[3].x;
            acc[e][1] += w.x * xb[0].y + w.y * xb[1].y + w.z * xb[2].y + w.w * xb[3].y;
            acc[e][2] += w.x * xb[0].z + w.y * xb[1].z + w.z * xb[2].z + w.w * xb[3].z;
            acc[e][3] += w.x * xb[0].w + w.y * xb[1].w + w.z * xb[2].w + w.w * xb[3].w;
        }
    }

    if (z == 1) {
#pragma unroll
        for (int e = 0; e < 4; e++)
            *(float4*)&g_g[((size_t)b * Ex + e0 + e) * Nx + n0] =
                make_float4(acc[e][0], acc[e][1], acc[e][2], acc[e][3]);
    } else if (z == 0) {
        // f: [b][n][32] bf16 hi/lo
#pragma unroll
        for (int t = 0; t < 4; t++) {
            const float v0 = acc[0][t], v1 = acc[1][t];
            const float v2 = acc[2][t], v3 = acc[3][t];
            const __nv_bfloat162 h01 = __float22bfloat162_rn(make_float2(v0, v1));
            const __nv_bfloat162 h23 = __float22bfloat162_rn(make_float2(v2, v3));
            const uint32_t l01 = packbf2(v0 - __bfloat162float(h01.x),
                                         v1 - __bfloat162float(h01.y));
            const uint32_t l23 = packbf2(v2 - __bfloat162float(h23.x),
                                         v3 - __bfloat162float(h23.y));
            const size_t base = ((size_t)b * Nx + (n0 + t)) * Ex + e0;
            *(uint2*)&g_f16h[base] = make_uint2(*(const uint32_t*)&h01,
                                                *(const uint32_t*)&h23);
            *(uint2*)&g_f16l[base] = make_uint2(l01, l23);
        }
    } else {
        // h: [b][e][n] bf16 hi/lo
#pragma unroll
        for (int e = 0; e < 4; e++) {
            const float v0 = acc[e][0], v1 = acc[e][1];
            const float v2 = acc[e][2], v3 = acc[e][3];
            const __nv_bfloat162 h01 = __float22bfloat162_rn(make_float2(v0, v1));
            const __nv_bfloat162 h23 = __float22bfloat162_rn(make_float2(v2, v3));
            const uint32_t l01 = packbf2(v0 - __bfloat162float(h01.x),
                                         v1 - __bfloat162float(h01.y));
            const uint32_t l23 = packbf2(v2 - __bfloat162float(h23.x),
                                         v3 - __bfloat162float(h23.y));
            const size_t base = ((size_t)b * Ex + (e0 + e)) * Nx + n0;
            *(uint2*)&g_h16h[base] = make_uint2(*(const uint32_t*)&h01,
                                                *(const uint32_t*)&h23);
            *(uint2*)&g_h16l[base] = make_uint2(l01, l23);
        }
    }
}

// ===========================================================================
// Kernel 2: mma.sync flash attention. grid (32, B), block 512 (16 warps).
// Register-staged tile prefetch: LDG for tile t+1 issued before computing t,
// STS happens next iteration -> global latency hidden behind the MMA work.
// ===========================================================================
#define FROW 80     // bytes per fh row (40 bf16)
#define HROW 272    // bytes per hh row (136 bf16)

__global__ __launch_bounds__(512, 1) void attn_mma_kernel()
{
    __shared__ __align__(128) uint8_t S[38912];
    uint8_t* fhP = S;                 // 128*80   = 10240
    uint8_t* flP = S + 10240;        // 10240
    uint8_t* hhP = S + 20480;        // 32*272   = 8704
    uint8_t* hlP = S + 29184;        // 8704

    const int tid  = threadIdx.x;
    const int w    = tid >> 5;
    const int lane = tid & 31;
    const int qt   = w & 7;
    const int kh   = w >> 3;
    const int b    = blockIdx.y;
    const int qw   = blockIdx.x * 128 + qt * 16;

    const float* gb = g_g + (size_t)b * Ex * Nx;
    const unsigned short* fHg = g_f16h + (size_t)b * Nx * Ex;
    const unsigned short* fLg = g_f16l + (size_t)b * Nx * Ex;
    const unsigned short* hHg = g_h16h + (size_t)b * Ex * Nx;
    const unsigned short* hLg = g_h16l + (size_t)b * Ex * Nx;

    const uint32_t fhA = smem_u32(fhP);
    const uint32_t flA = smem_u32(flP);
    const uint32_t hhA = smem_u32(hhP);
    const uint32_t hlA = smem_u32(hlP);

    const float LOG2E = 1.4426950408889634f;

    uint32_t gAh[2][4], gAl[2][4];
    {
        const int qa = qw + (lane >> 2);
#pragma unroll
        for (int ke = 0; ke < 2; ke++) {
#pragma unroll
            for (int r = 0; r < 4; r++) {
                const int row = qa + (r & 1) * 8;
                const int e   = ke * 16 + (r >> 1) * 8 + (lane & 3) * 2;
                const float v0 = gb[e * Nx + row] * LOG2E;
                const float v1 = gb[(e + 1) * Nx + row] * LOG2E;
                const __nv_bfloat162 hi2 = __float22bfloat162_rn(make_float2(v0, v1));
                gAh[ke][r] = *(const uint32_t*)&hi2;
                gAl[ke][r] = packbf2(v0 - __bfloat162float(hi2.x),
                                     v1 - __bfloat162float(hi2.y));
            }
        }
    }

    float Vac[4][4];
#pragma unroll
    for (int nt = 0; nt < 4; nt++)
#pragma unroll
        for (int r = 0; r < 4; r++) Vac[nt][r] = 0.f;
    float lsum0 = 0.f, lsum1 = 0.f;

    const int m = lane >> 3;
    const uint32_t fSel = (uint32_t)(((m >> 1) * 8 + (lane & 7)) * FROW + (m & 1) * 16);
    const uint32_t hSel = (uint32_t)(((m >> 1) * 8 + (lane & 7)) * HROW + (m & 1) * 16);

    // fill-role indices (per thread, fixed)
    const int fk = tid >> 2, fch = tid & 3;
    const int he = tid >> 4, hkc = (tid & 15) * 8;
    uint8_t* const fhDst = fhP + fk * FROW + fch * 16;
    uint8_t* const flDst = flP + fk * FROW + fch * 16;
    uint8_t* const hhDst = hhP + he * HROW + hkc * 2;
    uint8_t* const hlDst = hlP + he * HROW + hkc * 2;

    // prefetch tile 0
    uint4 rfh, rfl, rhh, rhl;
    {
        const size_t fsrc = (size_t)fk * Ex + fch * 8;
        const size_t hsrc = (size_t)he * Nx + hkc;
        rfh = *(const uint4*)(fHg + fsrc);
        rfl = *(const uint4*)(fLg + fsrc);
        rhh = *(const uint4*)(hHg + hsrc);
        rhl = *(const uint4*)(hLg + hsrc);
    }

    for (int t = 0; t < Nx / TK; t++) {
        __syncthreads();                 // prior tile's consumers done
        *(uint4*)fhDst = rfh;
        *(uint4*)flDst = rfl;
        *(uint4*)hhDst = rhh;
        *(uint4*)hlDst = rhl;
        __syncthreads();

        // prefetch tile t+1 (latency hidden behind this tile's compute)
        if (t + 1 < Nx / TK) {
            const int i1 = (t + 1) * TK;
            const size_t fsrc = (size_t)(i1 + fk) * Ex + fch * 8;
            const size_t hsrc = (size_t)he * Nx + i1 + hkc;
            rfh = *(const uint4*)(fHg + fsrc);
            rfl = *(const uint4*)(fLg + fsrc);
            rhh = *(const uint4*)(hHg + hsrc);
            rhl = *(const uint4*)(hLg + hsrc);
        }

#pragma unroll 1
        for (int kk = 0; kk < 4; kk++) {
            const uint32_t fTile = (uint32_t)((kh * 64 + kk * 16) * FROW) + fSel;
            float c0[4] = {0.f, 0.f, 0.f, 0.f};
            float c1[4] = {0.f, 0.f, 0.f, 0.f};

#pragma unroll
            for (int ke = 0; ke < 2; ke++) {
                uint32_t bh[4], bl[4];
                ldsm4(fhA + fTile + ke * 32, bh);
                ldsm4(flA + fTile + ke * 32, bl);
                mma16816(c0, gAh[ke], bh[0], bh[1]);
                mma16816(c1, gAh[ke], bh[2], bh[3]);
                mma16816(c0, gAl[ke], bh[0], bh[1]);
                mma16816(c1, gAl[ke], bh[2], bh[3]);
                mma16816(c0, gAh[ke], bl[0], bl[1]);
                mma16816(c1, gAh[ke], bl[2], bl[3]);
            }

            float p0[4], p1[4];
#pragma unroll
            for (int r = 0; r < 4; r++) { p0[r] = ex2(c0[r]); p1[r] = ex2(c1[r]); }
            lsum0 += (p0[0] + p0[1]) + (p1[0] + p1[1]);
            lsum1 += (p0[2] + p0[3]) + (p1[2] + p1[3]);

            uint32_t aPh[4], aPl[4];
            {
                const __nv_bfloat162 t0 = __float22bfloat162_rn(make_float2(p0[0], p0[1]));
                const __nv_bfloat162 t1 = __float22bfloat162_rn(make_float2(p0[2], p0[3]));
                const __nv_bfloat162 t2 = __float22bfloat162_rn(make_float2(p1[0], p1[1]));
                const __nv_bfloat162 t3 = __float22bfloat162_rn(make_float2(p1[2], p1[3]));
                aPh[0] = *(const uint32_t*)&t0;
                aPh[1] = *(const uint32_t*)&t1;
                aPh[2] = *(const uint32_t*)&t2;
                aPh[3] = *(const uint32_t*)&t3;
                aPl[0] = packbf2(p0[0] - __bfloat162float(t0.x), p0[1] - __bfloat162float(t0.y));
                aPl[1] = packbf2(p0[2] - __bfloat162float(t1.x), p0[3] - __bfloat162float(t1.y));
                aPl[2] = packbf2(p1[0] - __bfloat162float(t2.x), p1[1] - __bfloat162float(t2.y));
                aPl[3] = packbf2(p1[2] - __bfloat162float(t3.x), p1[3] - __bfloat162float(t3.y));
            }

            const uint32_t hTile = (uint32_t)(kh * 128 + kk * 32) + hSel;
            uint32_t b0[4], b1[4], d0[4], d1[4];
            ldsm4(hhA + hTile, b0);
            ldsm4(hhA + hTile + 16 * HROW, b1);
            ldsm4(hlA + hTile, d0);
            ldsm4(hlA + hTile + 16 * HROW, d1);
#pragma unroll
            for (int j = 0; j < 2; j++) {
                mma16816(Vac[j],   aPh, b0[2*j], b0[2*j+1]);
                mma16816(Vac[j],   aPl, b0[2*j], b0[2*j+1]);
                mma16816(Vac[j],   aPh, d0[2*j], d0[2*j+1]);
                mma16816(Vac[2+j], aPh, b1[2*j], b1[2*j+1]);
                mma16816(Vac[2+j], aPl, b1[2*j], b1[2*j+1]);
                mma16816(Vac[2+j], aPh, d1[2*j], d1[2*j+1]);
            }
        }
    }

    __syncthreads();
    float* Vbuf = (float*)S;               // [128][33] floats
    float* Lbuf = (float*)(S + 17408);     // 128 floats

    lsum0 += __shfl_xor_sync(0xffffffffu, lsum0, 1);
    lsum0 += __shfl_xor_sync(0xffffffffu, lsum0, 2);
    lsum1 += __shfl_xor_sync(0xffffffffu, lsum1, 1);
    lsum1 += __shfl_xor_sync(0xffffffffu, lsum1, 2);

    const int qrow = lane >> 2;
    if (kh == 1) {
#pragma unroll
        for (int nt = 0; nt < 4; nt++) {
            const int e = nt * 8 + (lane & 3) * 2;
            Vbuf[(qt * 16 + qrow) * 33 + e]         = Vac[nt][0];
            Vbuf[(qt * 16 + qrow) * 33 + e + 1]     = Vac[nt][1];
            Vbuf[(qt * 16 + qrow + 8) * 33 + e]     = Vac[nt][2];
            Vbuf[(qt * 16 + qrow + 8) * 33 + e + 1] = Vac[nt][3];
        }
        if ((lane & 3) == 0) {
            Lbuf[qt * 16 + qrow]     = lsum0;
            Lbuf[qt * 16 + qrow + 8] = lsum1;
        }
    }
    __syncthreads();
    if (kh == 0) {
        const float inv0 = 1.0f / (lsum0 + Lbuf[qt * 16 + qrow]);
        const float inv1 = 1.0f / (lsum1 + Lbuf[qt * 16 + qrow + 8]);
        float* vp = g_v + (size_t)b * Ex * Nx;
        const int q0 = qw + qrow;
#pragma unroll
        for (int nt = 0; nt < 4; nt++) {
            const int e = nt * 8 + (lane & 3) * 2;
            vp[e * Nx + q0] =
                (Vac[nt][0] + Vbuf[(qt * 16 + qrow) * 33 + e]) * inv0;
            vp[(e + 1) * Nx + q0] =
                (Vac[nt][1] + Vbuf[(qt * 16 + qrow) * 33 + e + 1]) * inv0;
            vp[e * Nx + q0 + 8] =
                (Vac[nt][2] + Vbuf[(qt * 16 + qrow + 8) * 33 + e]) * inv1;
            vp[(e + 1) * Nx + q0 + 8] =
                (Vac[nt][3] + Vbuf[(qt * 16 + qrow + 8) * 33 + e + 1]) * inv1;
        }
    }
}

// ===========================================================================
// Kernel 3: o = Wo @ v + bo ; y = 0.5*o + x ; gamma = 0.5
// grid (64, B) = 256 blocks, block 256.
// ===========================================================================
__global__ __launch_bounds__(256) void oproj_kernel(
    const float* __restrict__ x,
    const float* __restrict__ Wo, const float* __restrict__ bo,
    float* __restrict__ out_y, float* __restrict__ out_o,
    float* __restrict__ out_gamma)
{
    const int tid = threadIdx.x;
    const int tl  = tid & 31;
    const int cs  = tid >> 5;           // 0..7, warp-uniform
    const int n0  = blockIdx.x * 64 + tl * 2;
    const int b   = blockIdx.y;

    float2 vr[Ex];
    const float* vp = g_v + (size_t)b * Ex * Nx + n0;
#pragma unroll
    for (int e = 0; e < Ex; e++) vr[e] = *(const float2*)&vp[e * Nx];

    const float4* Wo4 = (const float4*)Wo;  // [Cx][Ex/4]
    const float* xp = x + (size_t)b * Cx * Nx + n0;
    float* yp = out_y + (size_t)b * Cx * Nx + n0;
    float* op = out_o ? (out_o + (size_t)b * Cx * Nx + n0) : nullptr;

    const int c0 = cs * 32;
#pragma unroll 4
    for (int ci = 0; ci < 32; ci++) {
        const int c = c0 + ci;
        float a0 = bo[c], a1 = a0;
#pragma unroll
        for (int e4 = 0; e4 < Ex / 4; e4++) {
            const float4 w = Wo4[c * (Ex / 4) + e4];
            a0 += w.x * vr[e4*4+0].x + w.y * vr[e4*4+1].x +
                  w.z * vr[e4*4+2].x + w.w * vr[e4*4+3].x;
            a1 += w.x * vr[e4*4+0].y + w.y * vr[e4*4+1].y +
                  w.z * vr[e4*4+2].y + w.w * vr[e4*4+3].y;
        }
        if (op) *(float2*)&op[c * Nx] = make_float2(a0, a1);
        const float2 xv = *(const float2*)&xp[c * Nx];
        *(float2*)&yp[c * Nx] = make_float2(0.5f * a0 + xv.x, 0.5f * a1 + xv.y);
    }

    if (out_gamma && blockIdx.x == 0 && blockIdx.y == 0 && threadIdx.x == 0)
        out_gamma[0] = 0.5f;
}

// ===========================================================================
extern "C" void kernel_launch(void* const* d_in, const int* in_sizes, int n_in,
                              void* d_out, int out_size)
{
    const float* x  = (const float*)d_in[0];
    const float* Wk = (const float*)d_in[1];
    const float* bk = (const float*)d_in[2];
    const float* Wq = (const float*)d_in[3];
    const float* bq = (const float*)d_in[4];
    const float* Wv = (const float*)d_in[5];
    const float* bv = (const float*)d_in[6];
    const float* Wo = (const float*)d_in[7];
    const float* bo = (const float*)d_in[8];

    const size_t BCN = (size_t)Bx * Cx * Nx;  // 4194304
    float* out = (float*)d_out;

    const bool full = ((size_t)out_size >= 2 * BCN + 1);
    float* out_y = out;
    float* out_o = full ? (out + BCN) : nullptr;
    float* out_g = full ? (out + 2 * BCN) : nullptr;

    proj_kernel<<<dim3(Nx / 128, Bx, 3), 256>>>(x, Wk, bk, Wq, bq, Wv, bv);
    attn_mma_kernel<<<dim3(Nx / 128, Bx), 512>>>();
    oproj_kernel<<<dim3(Nx / 64, Bx), 256>>>(x, Wo, bo, out_y, out_o, out_g);
}